// round 3
// baseline (speedup 1.0000x reference)
#include <cuda_runtime.h>
#include <cuda_bf16.h>
#include <cstdint>

// Problem constants
#define NB   64      // batch
#define TT   512     // time steps
#define DD   512     // input dim
#define HH   512     // hidden dim
#define G3   1536    // 3*H

// Scratch (device globals: allocation-free)
__device__ float g_xm[(size_t)2 * NB * TT * G3];   // [dir][n][t][3H], bias folded in
__device__ float g_h[2 * 2 * NB * HH];             // [dir][parity][n][h] ping-pong
__device__ unsigned g_arrive[2];
__device__ unsigned g_release[2];

// packed fp32x2 FMA (ptxas never auto-fuses this; PTX-only)
#define FMA2(d, a, b) asm("fma.rn.f32x2 %0, %1, %2, %0;" : "+l"(d) : "l"(a), "l"(b))

__device__ __forceinline__ float lo32(unsigned long long v) {
    return __uint_as_float((unsigned)(v & 0xffffffffull));
}
__device__ __forceinline__ float hi32(unsigned long long v) {
    return __uint_as_float((unsigned)(v >> 32));
}

// -----------------------------------------------------------------------------
// Init: zero h ping-pong buffers + barrier state
// -----------------------------------------------------------------------------
__global__ void init_kernel(float* h) {
    int i = blockIdx.x * blockDim.x + threadIdx.x;   // 128*256 = 32768 float4s
    reinterpret_cast<float4*>(h)[i] = make_float4(0.f, 0.f, 0.f, 0.f);
    if (i == 0) {
        g_arrive[0] = 0; g_arrive[1] = 0;
        g_release[0] = 0; g_release[1] = 0;
    }
}

// -----------------------------------------------------------------------------
// Input projection GEMM, f32x2 packed-K version.
//   xm[dir][m][c] = sum_k x'[m][k] * Wx[k][c] + bias[c]
// Tile: BM=128 (m), BJ=64 (c), BK=16 (8 k-pairs). 256 threads.
// SMEM k-pair-interleaved:
//   As[kp][2*i + (k&1)]  row = 260 floats (pad -> 1040B, 16B-aligned rows)
//   Bs[kp][2*j + (k&1)]  row = 132 floats (528B, 16B-aligned rows)
// Per thread: 8(i) x 4(j) f32x2 accumulators; acc.lo = even-k sum, acc.hi =
// odd-k sum; epilogue adds halves. Inner loop: 6 LDS.128 + 32 FMA2 per kp.
// Grid: (1536/64=24, 32768/128=256, 2)
// -----------------------------------------------------------------------------
#define XROW_A 260
#define XROW_B 132

__global__ __launch_bounds__(256, 2) void sgemm_xm_kernel(
    const float* __restrict__ x,
    const float* __restrict__ Wx_f, const float* __restrict__ Wx_b,
    const float* __restrict__ b_f,  const float* __restrict__ b_b,
    float* __restrict__ xm)
{
    const int dir = blockIdx.z;
    const float* __restrict__ Wx   = dir ? Wx_b : Wx_f;
    const float* __restrict__ bias = dir ? b_b  : b_f;
    float* __restrict__ C = xm + (size_t)dir * (NB * TT) * G3;

    __shared__ __align__(16) float As[8 * XROW_A];
    __shared__ __align__(16) float Bs[8 * XROW_B];

    const int t  = threadIdx.x;
    const int tx = t & 15;          // j group (4 cols)
    const int ty = t >> 4;          // i group (8 rows)

    const int mBase = blockIdx.y * 128;
    const int jBase = blockIdx.x * 64;

    // ---- A staging role: thread -> row ai, k-octet akq ----
    const int ai  = t >> 1;          // 0..127
    const int akq = (t & 1) * 8;     // 0 or 8
    const int am  = mBase + ai;
    const int an  = am >> 9;
    const int at0 = am & 511;
    const int ats = dir ? (TT - 1 - at0) : at0;
    const float* __restrict__ aRow = x + ((size_t)an * TT + ats) * DD;

    // ---- B staging role (threads < 128): kp = t>>4, jq = (t&15)*4 ----
    const int bkp = t >> 4;          // 0..7 (valid when t<128)
    const int bjq = (t & 15) * 4;

    const float4 biasv = *reinterpret_cast<const float4*>(&bias[jBase + tx * 4]);

    unsigned long long acc[8][4];
#pragma unroll
    for (int i = 0; i < 8; i++)
#pragma unroll
        for (int j = 0; j < 4; j++) acc[i][j] = 0ull;

    for (int k0 = 0; k0 < DD; k0 += 16) {
        // ---- stage A: 2 float4 -> 4 float2 pair-interleaved stores ----
#pragma unroll
        for (int q = 0; q < 2; q++) {
            const int k  = akq + 4 * q;
            const float4 v = *reinterpret_cast<const float4*>(&aRow[k0 + k]);
            const int kp = k >> 1;
            *reinterpret_cast<float2*>(&As[kp * XROW_A + 2 * ai])       = make_float2(v.x, v.y);
            *reinterpret_cast<float2*>(&As[(kp + 1) * XROW_A + 2 * ai]) = make_float2(v.z, v.w);
        }
        // ---- stage B: interleave rows k0+2kp (even) and k0+2kp+1 (odd) ----
        if (t < 128) {
            const float* w0 = &Wx[(size_t)(k0 + 2 * bkp) * G3 + jBase + bjq];
            const float4 e = *reinterpret_cast<const float4*>(w0);
            const float4 o = *reinterpret_cast<const float4*>(w0 + G3);
            float2* dst = reinterpret_cast<float2*>(&Bs[bkp * XROW_B + 2 * bjq]);
            dst[0] = make_float2(e.x, o.x);
            dst[1] = make_float2(e.y, o.y);
            dst[2] = make_float2(e.z, o.z);
            dst[3] = make_float2(e.w, o.w);
        }
        __syncthreads();

#pragma unroll
        for (int kp = 0; kp < 8; kp++) {
            unsigned long long a[8], b[4];
            const ulonglong2* ap =
                reinterpret_cast<const ulonglong2*>(&As[kp * XROW_A + 16 * ty]);
#pragma unroll
            for (int q = 0; q < 4; q++) {
                const ulonglong2 v = ap[q];
                a[2 * q] = v.x; a[2 * q + 1] = v.y;
            }
            const ulonglong2* bp =
                reinterpret_cast<const ulonglong2*>(&Bs[kp * XROW_B + 8 * tx]);
#pragma unroll
            for (int q = 0; q < 2; q++) {
                const ulonglong2 v = bp[q];
                b[2 * q] = v.x; b[2 * q + 1] = v.y;
            }
#pragma unroll
            for (int i = 0; i < 8; i++)
#pragma unroll
                for (int j = 0; j < 4; j++)
                    FMA2(acc[i][j], a[i], b[j]);
        }
        __syncthreads();
    }

    // ---- epilogue: fold even/odd halves, add bias, store float4 ----
#pragma unroll
    for (int i = 0; i < 8; i++) {
        float4 o;
        o.x = lo32(acc[i][0]) + hi32(acc[i][0]) + biasv.x;
        o.y = lo32(acc[i][1]) + hi32(acc[i][1]) + biasv.y;
        o.z = lo32(acc[i][2]) + hi32(acc[i][2]) + biasv.z;
        o.w = lo32(acc[i][3]) + hi32(acc[i][3]) + biasv.w;
        const int m = mBase + ty * 8 + i;
        *reinterpret_cast<float4*>(&C[(size_t)m * G3 + jBase + tx * 4]) = o;
    }
}

// -----------------------------------------------------------------------------
// Persistent recurrence kernel (unchanged from R2 — passing, ~6us/step).
// Grid: dim3(64, 2) = 128 blocks, 256 threads. Block = (dir, 8 hidden units).
// -----------------------------------------------------------------------------
#define W2T_FLOATS   (24 * 512)          // 12288
#define H2_ROW       132                 // 64*2 + 4 pad floats
#define H2_FLOATS    (256 * H2_ROW)      // 33792
#define RED_FLOATS   (24 * 64)           // 1536
#define PERSIST_SMEM ((W2T_FLOATS + H2_FLOATS + RED_FLOATS) * 4)

__global__ __launch_bounds__(256, 1) void gru_persist_kernel(
    const float* __restrict__ Wh_f, const float* __restrict__ Wh_b,
    const float* __restrict__ xm,   float* __restrict__ h_buf,
    float* __restrict__ out)
{
    extern __shared__ float sm[];
    float* w2t = sm;                          // [24][512]
    float* h2f = sm + W2T_FLOATS;             // [256][132]
    float* red = sm + W2T_FLOATS + H2_FLOATS; // [24][64]

    const int dir = blockIdx.y;
    const int j0  = blockIdx.x * 8;
    const float* __restrict__ Wh = dir ? Wh_b : Wh_f;
    const int t = threadIdx.x;

    // ---- load W slice once: w2t[c][k] = Wh[k][(c>>3)*512 + j0 + (c&7)] ----
    for (int idx = t; idx < 24 * 512; idx += 256) {
        const int c = idx >> 9;
        const int k = idx & 511;
        w2t[c * 512 + k] = Wh[(size_t)k * G3 + (c >> 3) * HH + j0 + (c & 7)];
    }
    __syncthreads();

    // fixed per-thread roles
    const int w    = t >> 5;        // warp
    const int l    = t & 31;        // lane
    const int half = w >> 2;        // split-K half
    const int cb   = (w & 3) * 6;   // column base (6 cols)

    const int n_st = t >> 2;
    const int kq   = (t & 3) * 4;

    const int n_g = t >> 3;
    const int jj  = t & 7;
    const int jgl = j0 + jj;

    const float* xmd = xm + (size_t)dir * (NB * TT) * G3;

    for (int s = 0; s < TT; s++) {
        const int p = s & 1;
        const float* __restrict__ hprev = h_buf + ((size_t)dir * 2 + p)       * (NB * HH);
        float*       __restrict__ hnext = h_buf + ((size_t)dir * 2 + (p ^ 1)) * (NB * HH);

        // ---- prefetch xm gate inputs for this step ----
        const float* xr0 = &xmd[(((size_t)n_g)        * TT + s) * G3 + jgl];
        const float* xr1 = &xmd[(((size_t)n_g + 32)   * TT + s) * G3 + jgl];
        const float pxz0 = __ldg(xr0);
        const float pxr0 = __ldg(xr0 + HH);
        const float pxg0 = __ldg(xr0 + 2 * HH);
        const float pxz1 = __ldg(xr1);
        const float pxr1 = __ldg(xr1 + HH);
        const float pxg1 = __ldg(xr1 + 2 * HH);

        // ---- stage h_prev into h2 (pair layout over k) ----
#pragma unroll
        for (int k = kq; k < HH; k += 16) {
            const float4 v = *reinterpret_cast<const float4*>(&hprev[n_st * HH + k]);
            const int kp = k >> 1;
            *reinterpret_cast<float2*>(&h2f[kp * H2_ROW + 2 * n_st])       = make_float2(v.x, v.y);
            *reinterpret_cast<float2*>(&h2f[(kp + 1) * H2_ROW + 2 * n_st]) = make_float2(v.z, v.w);
        }
        __syncthreads();

        // ---- f32x2 GEMM: 6 cols x 2 n per thread, split-K over halves ----
        unsigned long long acc[12];
#pragma unroll
        for (int i = 0; i < 12; i++) acc[i] = 0ull;

        const int kpBeg = half * 128;
        for (int kp0 = kpBeg; kp0 < kpBeg + 128; kp0 += 4) {
            unsigned long long wv[6][4];
#pragma unroll
            for (int cc = 0; cc < 6; cc++) {
                const ulonglong2 wa = *reinterpret_cast<const ulonglong2*>(
                    &w2t[(cb + cc) * 512 + kp0 * 2]);
                const ulonglong2 wb = *reinterpret_cast<const ulonglong2*>(
                    &w2t[(cb + cc) * 512 + kp0 * 2 + 4]);
                wv[cc][0] = wa.x; wv[cc][1] = wa.y;
                wv[cc][2] = wb.x; wv[cc][3] = wb.y;
            }
#pragma unroll
            for (int q = 0; q < 4; q++) {
                const int kp = kp0 + q;
                const unsigned long long h0 =
                    *reinterpret_cast<const unsigned long long*>(&h2f[kp * H2_ROW + 2 * l]);
                const unsigned long long h1 =
                    *reinterpret_cast<const unsigned long long*>(&h2f[kp * H2_ROW + 2 * l + 64]);
#pragma unroll
                for (int cc = 0; cc < 6; cc++) {
                    FMA2(acc[cc * 2 + 0], wv[cc][q], h0);
                    FMA2(acc[cc * 2 + 1], wv[cc][q], h1);
                }
            }
        }

        // ---- split-K reduction into red[c][n] ----
        if (half == 1) {
#pragma unroll
            for (int cc = 0; cc < 6; cc++) {
                red[(cb + cc) * 64 + l]      = lo32(acc[cc * 2 + 0]) + hi32(acc[cc * 2 + 0]);
                red[(cb + cc) * 64 + l + 32] = lo32(acc[cc * 2 + 1]) + hi32(acc[cc * 2 + 1]);
            }
        }
        __syncthreads();
        if (half == 0) {
#pragma unroll
            for (int cc = 0; cc < 6; cc++) {
                const int i0 = (cb + cc) * 64 + l;
                const int i1 = i0 + 32;
                red[i0] = red[i0] + lo32(acc[cc * 2 + 0]) + hi32(acc[cc * 2 + 0]);
                red[i1] = red[i1] + lo32(acc[cc * 2 + 1]) + hi32(acc[cc * 2 + 1]);
            }
        }
        __syncthreads();

        // ---- gates: 2 (n, jj) pairs per thread ----
        const int t_out = dir ? (TT - 1 - s) : s;
        {
            const float hz0 = red[jj * 64 + n_g];
            const float hr0 = red[(8 + jj) * 64 + n_g];
            const float hg0 = red[(16 + jj) * 64 + n_g];
            const float hp0 = h2f[(jgl >> 1) * H2_ROW + 2 * n_g + (jgl & 1)];
            const float z0 = 1.f / (1.f + __expf(-(pxz0 + hz0)));
            const float r0 = 1.f / (1.f + __expf(-(pxr0 + hr0)));
            const float gg0 = tanhf(pxg0 + r0 * hg0);
            const float ht0 = (1.f - z0) * gg0 + z0 * hp0;
            hnext[n_g * HH + jgl] = ht0;
            out[((size_t)n_g * TT + t_out) * (2 * HH) + dir * HH + jgl] = ht0;

            const int n1 = n_g + 32;
            const float hz1 = red[jj * 64 + n1];
            const float hr1 = red[(8 + jj) * 64 + n1];
            const float hg1 = red[(16 + jj) * 64 + n1];
            const float hp1 = h2f[(jgl >> 1) * H2_ROW + 2 * n1 + (jgl & 1)];
            const float z1 = 1.f / (1.f + __expf(-(pxz1 + hz1)));
            const float r1 = 1.f / (1.f + __expf(-(pxr1 + hr1)));
            const float gg1 = tanhf(pxg1 + r1 * hg1);
            const float ht1 = (1.f - z1) * gg1 + z1 * hp1;
            hnext[n1 * HH + jgl] = ht1;
            out[((size_t)n1 * TT + t_out) * (2 * HH) + dir * HH + jgl] = ht1;
        }

        // ---- per-direction grid barrier (64 blocks) ----
        __syncthreads();
        __threadfence();
        if (t == 0) {
            const unsigned old = atomicAdd(&g_arrive[dir], 1);
            if (old == 63) {
                g_arrive[dir] = 0;
                __threadfence();
                atomicExch(&g_release[dir], (unsigned)(s + 1));
            } else {
                while (*((volatile unsigned*)&g_release[dir]) < (unsigned)(s + 1)) { }
            }
        }
        __syncthreads();
        __threadfence();
    }
}

// -----------------------------------------------------------------------------
// Launch
// -----------------------------------------------------------------------------
extern "C" void kernel_launch(void* const* d_in, const int* in_sizes, int n_in,
                              void* d_out, int out_size)
{
    (void)in_sizes; (void)n_in; (void)out_size;
    const float* x   = (const float*)d_in[0];
    const float* Wxf = (const float*)d_in[1];
    const float* Whf = (const float*)d_in[2];
    const float* bf  = (const float*)d_in[3];
    const float* Wxb = (const float*)d_in[4];
    const float* Whb = (const float*)d_in[5];
    const float* bb  = (const float*)d_in[6];
    float* out = (float*)d_out;

    float *xm, *hb;
    cudaGetSymbolAddress((void**)&xm, g_xm);
    cudaGetSymbolAddress((void**)&hb, g_h);

    cudaFuncSetAttribute(gru_persist_kernel,
                         cudaFuncAttributeMaxDynamicSharedMemorySize,
                         PERSIST_SMEM);

    // 1) h0 = 0, barrier state = 0
    init_kernel<<<128, 256>>>(hb);

    // 2) input projections (both directions), bias folded, f32x2 GEMM
    sgemm_xm_kernel<<<dim3(24, 256, 2), 256>>>(x, Wxf, Wxb, bf, bb, xm);

    // 3) persistent recurrence (all 512 steps, both dirs)
    gru_persist_kernel<<<dim3(64, 2), 256, PERSIST_SMEM>>>(
        Whf, Whb, xm, hb, out);
}

// round 4
// speedup vs baseline: 1.0493x; 1.0493x over previous
#include <cuda_runtime.h>
#include <cuda_bf16.h>
#include <cstdint>

// Problem constants
#define NB   64      // batch
#define TT   512     // time steps
#define DD   512     // input dim
#define HH   512     // hidden dim
#define G3   1536    // 3*H

// Scratch (device globals: allocation-free)
__device__ float g_xm[(size_t)2 * NB * TT * G3];   // [dir][n][t][3H], bias folded in
__device__ float g_h[2 * 2 * NB * HH];             // [dir][parity][n][h] ping-pong
__device__ unsigned g_arrive[2];
__device__ unsigned g_release[2];

// packed fp32x2 FMA (PTX-only; used in recurrence kernel)
#define FMA2(d, a, b) asm("fma.rn.f32x2 %0, %1, %2, %0;" : "+l"(d) : "l"(a), "l"(b))

__device__ __forceinline__ float lo32(unsigned long long v) {
    return __uint_as_float((unsigned)(v & 0xffffffffull));
}
__device__ __forceinline__ float hi32(unsigned long long v) {
    return __uint_as_float((unsigned)(v >> 32));
}

__device__ __forceinline__ unsigned f2tf32(float x) {
    unsigned r;
    asm("cvt.rna.tf32.f32 %0, %1;" : "=r"(r) : "f"(x));
    return r;
}

__device__ __forceinline__ void mma_tf32(float& c0, float& c1, float& c2, float& c3,
                                         unsigned a0, unsigned a1, unsigned a2, unsigned a3,
                                         unsigned b0, unsigned b1) {
    asm volatile(
        "mma.sync.aligned.m16n8k8.row.col.f32.tf32.tf32.f32 "
        "{%0,%1,%2,%3}, {%4,%5,%6,%7}, {%8,%9}, {%0,%1,%2,%3};"
        : "+f"(c0), "+f"(c1), "+f"(c2), "+f"(c3)
        : "r"(a0), "r"(a1), "r"(a2), "r"(a3), "r"(b0), "r"(b1));
}

// -----------------------------------------------------------------------------
// Init: zero h ping-pong buffers + barrier state
// -----------------------------------------------------------------------------
__global__ void init_kernel(float* h) {
    int i = blockIdx.x * blockDim.x + threadIdx.x;   // 128*256 = 32768 float4s
    reinterpret_cast<float4*>(h)[i] = make_float4(0.f, 0.f, 0.f, 0.f);
    if (i == 0) {
        g_arrive[0] = 0; g_arrive[1] = 0;
        g_release[0] = 0; g_release[1] = 0;
    }
}

// -----------------------------------------------------------------------------
// Input projection GEMM via tf32 tensor cores with 3xTF32 split:
//   xm = x_hi*W_hi + x_lo*W_hi + x_hi*W_lo + bias  (error ~1e-6)
// Tile BM=128, BN=128, BK=16; 256 threads (8 warps), warp tile 32x64.
// SMEM holds fragments in mma-lane-permuted layout:
//   A frag block [mtile(8)*kstep(2)][lane(32)][reg(4)]  (hi and lo)
//   B frag block [kstep(2)*ntpair(8)][lane(32)][reg(4)] (hi and lo)
// Mainloop reads are conflict-free LDS.128; MMA-bound.
// Grid: (12, 256, 2).
// -----------------------------------------------------------------------------
__global__ __launch_bounds__(256, 2) void sgemm_xm_tf32_kernel(
    const float* __restrict__ x,
    const float* __restrict__ Wx_f, const float* __restrict__ Wx_b,
    const float* __restrict__ b_f,  const float* __restrict__ b_b,
    float* __restrict__ xm)
{
    const int dir = blockIdx.z;
    const float* __restrict__ Wx   = dir ? Wx_b : Wx_f;
    const float* __restrict__ bias = dir ? b_b  : b_f;
    float* __restrict__ C = xm + (size_t)dir * (NB * TT) * G3;

    __shared__ __align__(16) unsigned AsH[16 * 32 * 4];  // 8 mtile * 2 kstep
    __shared__ __align__(16) unsigned AsL[16 * 32 * 4];
    __shared__ __align__(16) unsigned BsH[16 * 32 * 4];  // 2 kstep * 8 ntpair
    __shared__ __align__(16) unsigned BsL[16 * 32 * 4];

    const int t = threadIdx.x;
    const int w = t >> 5;            // warp 0..7
    const int l = t & 31;            // lane
    const int warp_m = w >> 1;       // 0..3  -> rows warp_m*32
    const int warp_n = w & 1;        // 0..1  -> cols warp_n*64
    const int gid = l >> 2;
    const int tig = l & 3;

    const int mBase = blockIdx.y * 128;
    const int jBase = blockIdx.x * 128;

    // ---- A staging role: row = t>>1, k half = t&1 ----
    const int aRowL = t >> 1;            // 0..127
    const int aKh   = t & 1;             // kstep
    const int am    = mBase + aRowL;
    const int an    = am >> 9;
    const int at0   = am & 511;
    const int ats   = dir ? (TT - 1 - at0) : at0;
    const float* __restrict__ aPtr = x + ((size_t)an * TT + ats) * DD + aKh * 8;
    const int aMtile = aRowL >> 4;
    const int aGid   = aRowL & 7;
    const int aHi8   = (aRowL >> 3) & 1;
    const int aFragB = (aMtile * 2 + aKh) * 128;   // *32 lanes *4 regs

    // ---- B staging role: kk = t>>4, ncol = (t&15)*8 ----
    const int bKk    = t >> 4;           // 0..15
    const int bKstep = bKk >> 3;
    const int bKrem  = bKk & 7;
    const int bTig   = bKrem & 3;
    const int bHi4   = bKrem >> 2;
    const int bNt    = t & 15;           // ntile
    const int bPair  = bNt >> 1;
    const int bOdd   = bNt & 1;
    const float* __restrict__ bPtr = Wx + (size_t)bKk * G3 + jBase + bNt * 8;
    const int bFragB = (bKstep * 8 + bPair) * 128;

    float acc[2][8][4];
#pragma unroll
    for (int mt = 0; mt < 2; mt++)
#pragma unroll
        for (int nt = 0; nt < 8; nt++)
#pragma unroll
            for (int r = 0; r < 4; r++) acc[mt][nt][r] = 0.f;

    for (int k0 = 0; k0 < DD; k0 += 16) {
        // ---- stage A: 8 floats -> hi/lo frags (scatter STS) ----
        {
            const float4 v0 = *reinterpret_cast<const float4*>(aPtr + k0);
            const float4 v1 = *reinterpret_cast<const float4*>(aPtr + k0 + 4);
            const float vals[8] = {v0.x, v0.y, v0.z, v0.w, v1.x, v1.y, v1.z, v1.w};
#pragma unroll
            for (int j = 0; j < 8; j++) {
                const int tg  = j & 3;
                const int h4  = j >> 2;
                const int off = aFragB + (aGid * 4 + tg) * 4 + aHi8 + 2 * h4;
                const unsigned hi = f2tf32(vals[j]);
                AsH[off] = hi;
                AsL[off] = f2tf32(vals[j] - __uint_as_float(hi));
            }
        }
        // ---- stage B ----
        {
            const float4 v0 = *reinterpret_cast<const float4*>(bPtr + (size_t)k0 * G3);
            const float4 v1 = *reinterpret_cast<const float4*>(bPtr + (size_t)k0 * G3 + 4);
            const float vals[8] = {v0.x, v0.y, v0.z, v0.w, v1.x, v1.y, v1.z, v1.w};
#pragma unroll
            for (int j = 0; j < 8; j++) {
                const int off = bFragB + (j * 4 + bTig) * 4 + bHi4 + 2 * bOdd;
                const unsigned hi = f2tf32(vals[j]);
                BsH[off] = hi;
                BsL[off] = f2tf32(vals[j] - __uint_as_float(hi));
            }
        }
        __syncthreads();

#pragma unroll
        for (int ks = 0; ks < 2; ks++) {
            uint4 ah[2], al[2];
#pragma unroll
            for (int mt = 0; mt < 2; mt++) {
                const int fi = ((warp_m * 2 + mt) * 2 + ks) * 32 + l;
                ah[mt] = reinterpret_cast<const uint4*>(AsH)[fi];
                al[mt] = reinterpret_cast<const uint4*>(AsL)[fi];
            }
#pragma unroll
            for (int np = 0; np < 4; np++) {
                const int fi = (ks * 8 + warp_n * 4 + np) * 32 + l;
                const uint4 bh = reinterpret_cast<const uint4*>(BsH)[fi];
                const uint4 bl = reinterpret_cast<const uint4*>(BsL)[fi];
#pragma unroll
                for (int mt = 0; mt < 2; mt++) {
                    float* c0 = acc[mt][2 * np];
                    float* c1 = acc[mt][2 * np + 1];
                    // even ntile: b regs (x=b0,y=b1); odd: (z,w)
                    mma_tf32(c0[0], c0[1], c0[2], c0[3], ah[mt].x, ah[mt].y, ah[mt].z, ah[mt].w, bh.x, bh.y);
                    mma_tf32(c0[0], c0[1], c0[2], c0[3], al[mt].x, al[mt].y, al[mt].z, al[mt].w, bh.x, bh.y);
                    mma_tf32(c0[0], c0[1], c0[2], c0[3], ah[mt].x, ah[mt].y, ah[mt].z, ah[mt].w, bl.x, bl.y);
                    mma_tf32(c1[0], c1[1], c1[2], c1[3], ah[mt].x, ah[mt].y, ah[mt].z, ah[mt].w, bh.z, bh.w);
                    mma_tf32(c1[0], c1[1], c1[2], c1[3], al[mt].x, al[mt].y, al[mt].z, al[mt].w, bh.z, bh.w);
                    mma_tf32(c1[0], c1[1], c1[2], c1[3], ah[mt].x, ah[mt].y, ah[mt].z, ah[mt].w, bl.z, bl.w);
                }
            }
        }
        __syncthreads();
    }

    // ---- epilogue: bias + store (c0,c1)/(c2,c3) as float2 ----
#pragma unroll
    for (int mt = 0; mt < 2; mt++) {
        const int m0 = mBase + warp_m * 32 + mt * 16 + gid;
        const int m1 = m0 + 8;
#pragma unroll
        for (int nt = 0; nt < 8; nt++) {
            const int col = jBase + warp_n * 64 + nt * 8 + tig * 2;
            const float2 bv = *reinterpret_cast<const float2*>(&bias[col]);
            float2 o0, o1;
            o0.x = acc[mt][nt][0] + bv.x;  o0.y = acc[mt][nt][1] + bv.y;
            o1.x = acc[mt][nt][2] + bv.x;  o1.y = acc[mt][nt][3] + bv.y;
            *reinterpret_cast<float2*>(&C[(size_t)m0 * G3 + col]) = o0;
            *reinterpret_cast<float2*>(&C[(size_t)m1 * G3 + col]) = o1;
        }
    }
}

// -----------------------------------------------------------------------------
// Persistent recurrence kernel (unchanged — passing, ~6us/step).
// Grid: dim3(64, 2) = 128 blocks, 256 threads. Block = (dir, 8 hidden units).
// -----------------------------------------------------------------------------
#define W2T_FLOATS   (24 * 512)          // 12288
#define H2_ROW       132                 // 64*2 + 4 pad floats
#define H2_FLOATS    (256 * H2_ROW)      // 33792
#define RED_FLOATS   (24 * 64)           // 1536
#define PERSIST_SMEM ((W2T_FLOATS + H2_FLOATS + RED_FLOATS) * 4)

__global__ __launch_bounds__(256, 1) void gru_persist_kernel(
    const float* __restrict__ Wh_f, const float* __restrict__ Wh_b,
    const float* __restrict__ xm,   float* __restrict__ h_buf,
    float* __restrict__ out)
{
    extern __shared__ float sm[];
    float* w2t = sm;                          // [24][512]
    float* h2f = sm + W2T_FLOATS;             // [256][132]
    float* red = sm + W2T_FLOATS + H2_FLOATS; // [24][64]

    const int dir = blockIdx.y;
    const int j0  = blockIdx.x * 8;
    const float* __restrict__ Wh = dir ? Wh_b : Wh_f;
    const int t = threadIdx.x;

    // ---- load W slice once ----
    for (int idx = t; idx < 24 * 512; idx += 256) {
        const int c = idx >> 9;
        const int k = idx & 511;
        w2t[c * 512 + k] = Wh[(size_t)k * G3 + (c >> 3) * HH + j0 + (c & 7)];
    }
    __syncthreads();

    const int w    = t >> 5;
    const int l    = t & 31;
    const int half = w >> 2;
    const int cb   = (w & 3) * 6;

    const int n_st = t >> 2;
    const int kq   = (t & 3) * 4;

    const int n_g = t >> 3;
    const int jj  = t & 7;
    const int jgl = j0 + jj;

    const float* xmd = xm + (size_t)dir * (NB * TT) * G3;

    for (int s = 0; s < TT; s++) {
        const int p = s & 1;
        const float* __restrict__ hprev = h_buf + ((size_t)dir * 2 + p)       * (NB * HH);
        float*       __restrict__ hnext = h_buf + ((size_t)dir * 2 + (p ^ 1)) * (NB * HH);

        // ---- prefetch xm gate inputs ----
        const float* xr0 = &xmd[(((size_t)n_g)        * TT + s) * G3 + jgl];
        const float* xr1 = &xmd[(((size_t)n_g + 32)   * TT + s) * G3 + jgl];
        const float pxz0 = __ldg(xr0);
        const float pxr0 = __ldg(xr0 + HH);
        const float pxg0 = __ldg(xr0 + 2 * HH);
        const float pxz1 = __ldg(xr1);
        const float pxr1 = __ldg(xr1 + HH);
        const float pxg1 = __ldg(xr1 + 2 * HH);

        // ---- stage h_prev (pair layout over k) ----
#pragma unroll
        for (int k = kq; k < HH; k += 16) {
            const float4 v = *reinterpret_cast<const float4*>(&hprev[n_st * HH + k]);
            const int kp = k >> 1;
            *reinterpret_cast<float2*>(&h2f[kp * H2_ROW + 2 * n_st])       = make_float2(v.x, v.y);
            *reinterpret_cast<float2*>(&h2f[(kp + 1) * H2_ROW + 2 * n_st]) = make_float2(v.z, v.w);
        }
        __syncthreads();

        // ---- f32x2 GEMM: 6 cols x 2 n per thread, split-K halves ----
        unsigned long long acc[12];
#pragma unroll
        for (int i = 0; i < 12; i++) acc[i] = 0ull;

        const int kpBeg = half * 128;
        for (int kp0 = kpBeg; kp0 < kpBeg + 128; kp0 += 4) {
            unsigned long long wv[6][4];
#pragma unroll
            for (int cc = 0; cc < 6; cc++) {
                const ulonglong2 wa = *reinterpret_cast<const ulonglong2*>(
                    &w2t[(cb + cc) * 512 + kp0 * 2]);
                const ulonglong2 wb = *reinterpret_cast<const ulonglong2*>(
                    &w2t[(cb + cc) * 512 + kp0 * 2 + 4]);
                wv[cc][0] = wa.x; wv[cc][1] = wa.y;
                wv[cc][2] = wb.x; wv[cc][3] = wb.y;
            }
#pragma unroll
            for (int q = 0; q < 4; q++) {
                const int kp = kp0 + q;
                const unsigned long long h0 =
                    *reinterpret_cast<const unsigned long long*>(&h2f[kp * H2_ROW + 2 * l]);
                const unsigned long long h1 =
                    *reinterpret_cast<const unsigned long long*>(&h2f[kp * H2_ROW + 2 * l + 64]);
#pragma unroll
                for (int cc = 0; cc < 6; cc++) {
                    FMA2(acc[cc * 2 + 0], wv[cc][q], h0);
                    FMA2(acc[cc * 2 + 1], wv[cc][q], h1);
                }
            }
        }

        // ---- split-K reduction ----
        if (half == 1) {
#pragma unroll
            for (int cc = 0; cc < 6; cc++) {
                red[(cb + cc) * 64 + l]      = lo32(acc[cc * 2 + 0]) + hi32(acc[cc * 2 + 0]);
                red[(cb + cc) * 64 + l + 32] = lo32(acc[cc * 2 + 1]) + hi32(acc[cc * 2 + 1]);
            }
        }
        __syncthreads();
        if (half == 0) {
#pragma unroll
            for (int cc = 0; cc < 6; cc++) {
                const int i0 = (cb + cc) * 64 + l;
                const int i1 = i0 + 32;
                red[i0] = red[i0] + lo32(acc[cc * 2 + 0]) + hi32(acc[cc * 2 + 0]);
                red[i1] = red[i1] + lo32(acc[cc * 2 + 1]) + hi32(acc[cc * 2 + 1]);
            }
        }
        __syncthreads();

        // ---- gates ----
        const int t_out = dir ? (TT - 1 - s) : s;
        {
            const float hz0 = red[jj * 64 + n_g];
            const float hr0 = red[(8 + jj) * 64 + n_g];
            const float hg0 = red[(16 + jj) * 64 + n_g];
            const float hp0 = h2f[(jgl >> 1) * H2_ROW + 2 * n_g + (jgl & 1)];
            const float z0 = 1.f / (1.f + __expf(-(pxz0 + hz0)));
            const float r0 = 1.f / (1.f + __expf(-(pxr0 + hr0)));
            const float gg0 = tanhf(pxg0 + r0 * hg0);
            const float ht0 = (1.f - z0) * gg0 + z0 * hp0;
            hnext[n_g * HH + jgl] = ht0;
            out[((size_t)n_g * TT + t_out) * (2 * HH) + dir * HH + jgl] = ht0;

            const int n1 = n_g + 32;
            const float hz1 = red[jj * 64 + n1];
            const float hr1 = red[(8 + jj) * 64 + n1];
            const float hg1 = red[(16 + jj) * 64 + n1];
            const float hp1 = h2f[(jgl >> 1) * H2_ROW + 2 * n1 + (jgl & 1)];
            const float z1 = 1.f / (1.f + __expf(-(pxz1 + hz1)));
            const float r1 = 1.f / (1.f + __expf(-(pxr1 + hr1)));
            const float gg1 = tanhf(pxg1 + r1 * hg1);
            const float ht1 = (1.f - z1) * gg1 + z1 * hp1;
            hnext[n1 * HH + jgl] = ht1;
            out[((size_t)n1 * TT + t_out) * (2 * HH) + dir * HH + jgl] = ht1;
        }

        // ---- per-direction grid barrier ----
        __syncthreads();
        __threadfence();
        if (t == 0) {
            const unsigned old = atomicAdd(&g_arrive[dir], 1);
            if (old == 63) {
                g_arrive[dir] = 0;
                __threadfence();
                atomicExch(&g_release[dir], (unsigned)(s + 1));
            } else {
                while (*((volatile unsigned*)&g_release[dir]) < (unsigned)(s + 1)) { }
            }
        }
        __syncthreads();
        __threadfence();
    }
}

// -----------------------------------------------------------------------------
// Launch
// -----------------------------------------------------------------------------
extern "C" void kernel_launch(void* const* d_in, const int* in_sizes, int n_in,
                              void* d_out, int out_size)
{
    (void)in_sizes; (void)n_in; (void)out_size;
    const float* x   = (const float*)d_in[0];
    const float* Wxf = (const float*)d_in[1];
    const float* Whf = (const float*)d_in[2];
    const float* bf  = (const float*)d_in[3];
    const float* Wxb = (const float*)d_in[4];
    const float* Whb = (const float*)d_in[5];
    const float* bb  = (const float*)d_in[6];
    float* out = (float*)d_out;

    float *xm, *hb;
    cudaGetSymbolAddress((void**)&xm, g_xm);
    cudaGetSymbolAddress((void**)&hb, g_h);

    cudaFuncSetAttribute(gru_persist_kernel,
                         cudaFuncAttributeMaxDynamicSharedMemorySize,
                         PERSIST_SMEM);

    // 1) h0 = 0, barrier state = 0
    init_kernel<<<128, 256>>>(hb);

    // 2) input projections: tf32 tensor-core GEMM with 3xTF32 split
    sgemm_xm_tf32_kernel<<<dim3(12, 256, 2), 256>>>(x, Wxf, Wxb, bf, bb, xm);

    // 3) persistent recurrence (all 512 steps, both dirs)
    gru_persist_kernel<<<dim3(64, 2), 256, PERSIST_SMEM>>>(
        Whf, Whb, xm, hb, out);
}

// round 5
// speedup vs baseline: 1.2555x; 1.1965x over previous
#include <cuda_runtime.h>
#include <cuda_bf16.h>
#include <cstdint>

// Problem constants
#define NB   64      // batch
#define TT   512     // time steps
#define DD   512     // input dim
#define HH   512     // hidden dim
#define G3   1536    // 3*H

// Scratch (device globals: allocation-free)
__device__ float g_xm[(size_t)2 * NB * TT * G3];   // [dir][n][t][3H], bias folded in
__device__ float g_h[2 * 2 * NB * HH];             // [dir][parity][n][h] ping-pong
__device__ unsigned g_arrive[2];
__device__ unsigned g_release[2];

// packed fp32x2 FMA (PTX-only; used in recurrence kernel)
#define FMA2(d, a, b) asm("fma.rn.f32x2 %0, %1, %2, %0;" : "+l"(d) : "l"(a), "l"(b))

__device__ __forceinline__ float lo32(unsigned long long v) {
    return __uint_as_float((unsigned)(v & 0xffffffffull));
}
__device__ __forceinline__ float hi32(unsigned long long v) {
    return __uint_as_float((unsigned)(v >> 32));
}

// pack two floats into bf16x2: lower half = even_k, upper half = odd_k
__device__ __forceinline__ unsigned packbf(float odd_k, float even_k) {
    unsigned r;
    asm("cvt.rn.bf16x2.f32 %0, %1, %2;" : "=r"(r) : "f"(odd_k), "f"(even_k));
    return r;
}
// residual after bf16 rounding
__device__ __forceinline__ float bfres(float x) {
    return x - __bfloat162float(__float2bfloat16_rn(x));
}

__device__ __forceinline__ void mma_bf16(float* c,
                                         const unsigned* a,
                                         unsigned b0, unsigned b1) {
    asm volatile(
        "mma.sync.aligned.m16n8k16.row.col.f32.bf16.bf16.f32 "
        "{%0,%1,%2,%3}, {%4,%5,%6,%7}, {%8,%9}, {%0,%1,%2,%3};"
        : "+f"(c[0]), "+f"(c[1]), "+f"(c[2]), "+f"(c[3])
        : "r"(a[0]), "r"(a[1]), "r"(a[2]), "r"(a[3]), "r"(b0), "r"(b1));
}

// -----------------------------------------------------------------------------
// Init: zero h ping-pong buffers + barrier state
// -----------------------------------------------------------------------------
__global__ void init_kernel(float* h) {
    int i = blockIdx.x * blockDim.x + threadIdx.x;   // 128*256 = 32768 float4s
    reinterpret_cast<float4*>(h)[i] = make_float4(0.f, 0.f, 0.f, 0.f);
    if (i == 0) {
        g_arrive[0] = 0; g_arrive[1] = 0;
        g_release[0] = 0; g_release[1] = 0;
    }
}

// -----------------------------------------------------------------------------
// Input projection GEMM via bf16 tensor cores, 3-pass hi/lo split:
//   xm = x_hi*W_hi + x_lo*W_hi + x_hi*W_lo + bias     (rel err ~2^-16)
// Tile BM=128, BN=128, BK=16; 256 threads (8 warps), warp tile 32x64.
// SMEM: k-paired bf16x2 tiles in NATURAL layout (no fragment permutation):
//   As2[k2][m], Bs2[k2][n], k2 = k/2, row stride 136 uints (8 mod 32 ->
//   fragment LDS.32 with lanes at banks 8*tig+gid: conflict-free).
// Mainloop per warp per tile: 48 LDS.32 + 48 MMA -> MMA-bound.
// Grid: (12, 256, 2).
// -----------------------------------------------------------------------------
#define AST 136   // uint stride per k2 row (136 mod 32 == 8)

__global__ __launch_bounds__(256, 2) void sgemm_xm_bf16x3_kernel(
    const float* __restrict__ x,
    const float* __restrict__ Wx_f, const float* __restrict__ Wx_b,
    const float* __restrict__ b_f,  const float* __restrict__ b_b,
    float* __restrict__ xm)
{
    const int dir = blockIdx.z;
    const float* __restrict__ Wx   = dir ? Wx_b : Wx_f;
    const float* __restrict__ bias = dir ? b_b  : b_f;
    float* __restrict__ C = xm + (size_t)dir * (NB * TT) * G3;

    __shared__ __align__(16) unsigned AsH[8 * AST];
    __shared__ __align__(16) unsigned AsL[8 * AST];
    __shared__ __align__(16) unsigned BsH[8 * AST];
    __shared__ __align__(16) unsigned BsL[8 * AST];

    const int t = threadIdx.x;
    const int w = t >> 5;            // warp 0..7
    const int l = t & 31;            // lane
    const int warp_m = w >> 1;       // 0..3  -> rows warp_m*32
    const int warp_n = w & 1;        // 0..1  -> cols warp_n*64
    const int gid = l >> 2;          // group id 0..7
    const int tig = l & 3;           // thread in group

    const int mBase = blockIdx.y * 128;
    const int jBase = blockIdx.x * 128;

    // ---- A staging role: m = t&127, k octet = (t>>7)*8 ----
    const int aM  = t & 127;
    const int aKg = (t >> 7) * 8;
    const int am  = mBase + aM;
    const int an  = am >> 9;
    const int at0 = am & 511;
    const int ats = dir ? (TT - 1 - at0) : at0;
    const float* __restrict__ aPtr = x + ((size_t)an * TT + ats) * DD + aKg;
    const int aR0 = aKg >> 1;        // base k2 row (0 or 4)

    // ---- B staging role: k-pair = t>>5 (0..7), n quad = (t&31)*4 ----
    const int bKp = t >> 5;
    const int bN  = (t & 31) * 4;
    const float* __restrict__ bPtr = Wx + (size_t)(2 * bKp) * G3 + jBase + bN;

    float acc[2][8][4];
#pragma unroll
    for (int mt = 0; mt < 2; mt++)
#pragma unroll
        for (int nt = 0; nt < 8; nt++)
#pragma unroll
            for (int r = 0; r < 4; r++) acc[mt][nt][r] = 0.f;

    for (int k0 = 0; k0 < DD; k0 += 16) {
        // ---- stage A: 8 consecutive k for one m -> 4 hi + 4 lo bf16x2 ----
        {
            const float4 v0 = *reinterpret_cast<const float4*>(aPtr + k0);
            const float4 v1 = *reinterpret_cast<const float4*>(aPtr + k0 + 4);
            AsH[(aR0 + 0) * AST + aM] = packbf(v0.y, v0.x);
            AsH[(aR0 + 1) * AST + aM] = packbf(v0.w, v0.z);
            AsH[(aR0 + 2) * AST + aM] = packbf(v1.y, v1.x);
            AsH[(aR0 + 3) * AST + aM] = packbf(v1.w, v1.z);
            AsL[(aR0 + 0) * AST + aM] = packbf(bfres(v0.y), bfres(v0.x));
            AsL[(aR0 + 1) * AST + aM] = packbf(bfres(v0.w), bfres(v0.z));
            AsL[(aR0 + 2) * AST + aM] = packbf(bfres(v1.y), bfres(v1.x));
            AsL[(aR0 + 3) * AST + aM] = packbf(bfres(v1.w), bfres(v1.z));
        }
        // ---- stage B: rows k0+2bKp (even) and +1 (odd), 4 cols -> STS.128 ----
        {
            const float* p = bPtr + (size_t)k0 * G3;
            const float4 e = *reinterpret_cast<const float4*>(p);
            const float4 o = *reinterpret_cast<const float4*>(p + G3);
            uint4 hh, ll;
            hh.x = packbf(o.x, e.x); hh.y = packbf(o.y, e.y);
            hh.z = packbf(o.z, e.z); hh.w = packbf(o.w, e.w);
            ll.x = packbf(bfres(o.x), bfres(e.x));
            ll.y = packbf(bfres(o.y), bfres(e.y));
            ll.z = packbf(bfres(o.z), bfres(e.z));
            ll.w = packbf(bfres(o.w), bfres(e.w));
            *reinterpret_cast<uint4*>(&BsH[bKp * AST + bN]) = hh;
            *reinterpret_cast<uint4*>(&BsL[bKp * AST + bN]) = ll;
        }
        __syncthreads();

        // ---- fragment loads (conflict-free LDS.32) + MMAs ----
        unsigned ahi[2][4], alo[2][4];
#pragma unroll
        for (int mt = 0; mt < 2; mt++) {
            const int m0 = warp_m * 32 + mt * 16 + gid;
            ahi[mt][0] = AsH[tig * AST + m0];
            ahi[mt][1] = AsH[tig * AST + m0 + 8];
            ahi[mt][2] = AsH[(tig + 4) * AST + m0];
            ahi[mt][3] = AsH[(tig + 4) * AST + m0 + 8];
            alo[mt][0] = AsL[tig * AST + m0];
            alo[mt][1] = AsL[tig * AST + m0 + 8];
            alo[mt][2] = AsL[(tig + 4) * AST + m0];
            alo[mt][3] = AsL[(tig + 4) * AST + m0 + 8];
        }
#pragma unroll
        for (int nt = 0; nt < 8; nt++) {
            const int n0 = warp_n * 64 + nt * 8 + gid;
            const unsigned bh0 = BsH[tig * AST + n0];
            const unsigned bh1 = BsH[(tig + 4) * AST + n0];
            const unsigned bl0 = BsL[tig * AST + n0];
            const unsigned bl1 = BsL[(tig + 4) * AST + n0];
#pragma unroll
            for (int mt = 0; mt < 2; mt++) {
                mma_bf16(acc[mt][nt], ahi[mt], bh0, bh1);
                mma_bf16(acc[mt][nt], alo[mt], bh0, bh1);
                mma_bf16(acc[mt][nt], ahi[mt], bl0, bl1);
            }
        }
        __syncthreads();
    }

    // ---- epilogue: bias + store (c0,c1)/(c2,c3) as float2 ----
#pragma unroll
    for (int mt = 0; mt < 2; mt++) {
        const int m0 = mBase + warp_m * 32 + mt * 16 + gid;
        const int m1 = m0 + 8;
#pragma unroll
        for (int nt = 0; nt < 8; nt++) {
            const int col = jBase + warp_n * 64 + nt * 8 + tig * 2;
            const float2 bv = *reinterpret_cast<const float2*>(&bias[col]);
            float2 o0, o1;
            o0.x = acc[mt][nt][0] + bv.x;  o0.y = acc[mt][nt][1] + bv.y;
            o1.x = acc[mt][nt][2] + bv.x;  o1.y = acc[mt][nt][3] + bv.y;
            *reinterpret_cast<float2*>(&C[(size_t)m0 * G3 + col]) = o0;
            *reinterpret_cast<float2*>(&C[(size_t)m1 * G3 + col]) = o1;
        }
    }
}

// -----------------------------------------------------------------------------
// Persistent recurrence kernel (unchanged from R2 — proven, ~6us/step).
// Grid: dim3(64, 2) = 128 blocks, 256 threads. Block = (dir, 8 hidden units).
// -----------------------------------------------------------------------------
#define W2T_FLOATS   (24 * 512)          // 12288
#define H2_ROW       132                 // 64*2 + 4 pad floats
#define H2_FLOATS    (256 * H2_ROW)      // 33792
#define RED_FLOATS   (24 * 64)           // 1536
#define PERSIST_SMEM ((W2T_FLOATS + H2_FLOATS + RED_FLOATS) * 4)

__global__ __launch_bounds__(256, 1) void gru_persist_kernel(
    const float* __restrict__ Wh_f, const float* __restrict__ Wh_b,
    const float* __restrict__ xm,   float* __restrict__ h_buf,
    float* __restrict__ out)
{
    extern __shared__ float sm[];
    float* w2t = sm;                          // [24][512]
    float* h2f = sm + W2T_FLOATS;             // [256][132]
    float* red = sm + W2T_FLOATS + H2_FLOATS; // [24][64]

    const int dir = blockIdx.y;
    const int j0  = blockIdx.x * 8;
    const float* __restrict__ Wh = dir ? Wh_b : Wh_f;
    const int t = threadIdx.x;

    // ---- load W slice once ----
    for (int idx = t; idx < 24 * 512; idx += 256) {
        const int c = idx >> 9;
        const int k = idx & 511;
        w2t[c * 512 + k] = Wh[(size_t)k * G3 + (c >> 3) * HH + j0 + (c & 7)];
    }
    __syncthreads();

    const int w    = t >> 5;
    const int l    = t & 31;
    const int half = w >> 2;
    const int cb   = (w & 3) * 6;

    const int n_st = t >> 2;
    const int kq   = (t & 3) * 4;

    const int n_g = t >> 3;
    const int jj  = t & 7;
    const int jgl = j0 + jj;

    const float* xmd = xm + (size_t)dir * (NB * TT) * G3;

    for (int s = 0; s < TT; s++) {
        const int p = s & 1;
        const float* __restrict__ hprev = h_buf + ((size_t)dir * 2 + p)       * (NB * HH);
        float*       __restrict__ hnext = h_buf + ((size_t)dir * 2 + (p ^ 1)) * (NB * HH);

        // ---- prefetch xm gate inputs ----
        const float* xr0 = &xmd[(((size_t)n_g)        * TT + s) * G3 + jgl];
        const float* xr1 = &xmd[(((size_t)n_g + 32)   * TT + s) * G3 + jgl];
        const float pxz0 = __ldg(xr0);
        const float pxr0 = __ldg(xr0 + HH);
        const float pxg0 = __ldg(xr0 + 2 * HH);
        const float pxz1 = __ldg(xr1);
        const float pxr1 = __ldg(xr1 + HH);
        const float pxg1 = __ldg(xr1 + 2 * HH);

        // ---- stage h_prev (pair layout over k) ----
#pragma unroll
        for (int k = kq; k < HH; k += 16) {
            const float4 v = *reinterpret_cast<const float4*>(&hprev[n_st * HH + k]);
            const int kp = k >> 1;
            *reinterpret_cast<float2*>(&h2f[kp * H2_ROW + 2 * n_st])       = make_float2(v.x, v.y);
            *reinterpret_cast<float2*>(&h2f[(kp + 1) * H2_ROW + 2 * n_st]) = make_float2(v.z, v.w);
        }
        __syncthreads();

        // ---- f32x2 GEMM: 6 cols x 2 n per thread, split-K halves ----
        unsigned long long acc[12];
#pragma unroll
        for (int i = 0; i < 12; i++) acc[i] = 0ull;

        const int kpBeg = half * 128;
        for (int kp0 = kpBeg; kp0 < kpBeg + 128; kp0 += 4) {
            unsigned long long wv[6][4];
#pragma unroll
            for (int cc = 0; cc < 6; cc++) {
                const ulonglong2 wa = *reinterpret_cast<const ulonglong2*>(
                    &w2t[(cb + cc) * 512 + kp0 * 2]);
                const ulonglong2 wb = *reinterpret_cast<const ulonglong2*>(
                    &w2t[(cb + cc) * 512 + kp0 * 2 + 4]);
                wv[cc][0] = wa.x; wv[cc][1] = wa.y;
                wv[cc][2] = wb.x; wv[cc][3] = wb.y;
            }
#pragma unroll
            for (int q = 0; q < 4; q++) {
                const int kp = kp0 + q;
                const unsigned long long h0 =
                    *reinterpret_cast<const unsigned long long*>(&h2f[kp * H2_ROW + 2 * l]);
                const unsigned long long h1 =
                    *reinterpret_cast<const unsigned long long*>(&h2f[kp * H2_ROW + 2 * l + 64]);
#pragma unroll
                for (int cc = 0; cc < 6; cc++) {
                    FMA2(acc[cc * 2 + 0], wv[cc][q], h0);
                    FMA2(acc[cc * 2 + 1], wv[cc][q], h1);
                }
            }
        }

        // ---- split-K reduction ----
        if (half == 1) {
#pragma unroll
            for (int cc = 0; cc < 6; cc++) {
                red[(cb + cc) * 64 + l]      = lo32(acc[cc * 2 + 0]) + hi32(acc[cc * 2 + 0]);
                red[(cb + cc) * 64 + l + 32] = lo32(acc[cc * 2 + 1]) + hi32(acc[cc * 2 + 1]);
            }
        }
        __syncthreads();
        if (half == 0) {
#pragma unroll
            for (int cc = 0; cc < 6; cc++) {
                const int i0 = (cb + cc) * 64 + l;
                const int i1 = i0 + 32;
                red[i0] = red[i0] + lo32(acc[cc * 2 + 0]) + hi32(acc[cc * 2 + 0]);
                red[i1] = red[i1] + lo32(acc[cc * 2 + 1]) + hi32(acc[cc * 2 + 1]);
            }
        }
        __syncthreads();

        // ---- gates ----
        const int t_out = dir ? (TT - 1 - s) : s;
        {
            const float hz0 = red[jj * 64 + n_g];
            const float hr0 = red[(8 + jj) * 64 + n_g];
            const float hg0 = red[(16 + jj) * 64 + n_g];
            const float hp0 = h2f[(jgl >> 1) * H2_ROW + 2 * n_g + (jgl & 1)];
            const float z0 = 1.f / (1.f + __expf(-(pxz0 + hz0)));
            const float r0 = 1.f / (1.f + __expf(-(pxr0 + hr0)));
            const float gg0 = tanhf(pxg0 + r0 * hg0);
            const float ht0 = (1.f - z0) * gg0 + z0 * hp0;
            hnext[n_g * HH + jgl] = ht0;
            out[((size_t)n_g * TT + t_out) * (2 * HH) + dir * HH + jgl] = ht0;

            const int n1 = n_g + 32;
            const float hz1 = red[jj * 64 + n1];
            const float hr1 = red[(8 + jj) * 64 + n1];
            const float hg1 = red[(16 + jj) * 64 + n1];
            const float hp1 = h2f[(jgl >> 1) * H2_ROW + 2 * n1 + (jgl & 1)];
            const float z1 = 1.f / (1.f + __expf(-(pxz1 + hz1)));
            const float r1 = 1.f / (1.f + __expf(-(pxr1 + hr1)));
            const float gg1 = tanhf(pxg1 + r1 * hg1);
            const float ht1 = (1.f - z1) * gg1 + z1 * hp1;
            hnext[n1 * HH + jgl] = ht1;
            out[((size_t)n1 * TT + t_out) * (2 * HH) + dir * HH + jgl] = ht1;
        }

        // ---- per-direction grid barrier ----
        __syncthreads();
        __threadfence();
        if (t == 0) {
            const unsigned old = atomicAdd(&g_arrive[dir], 1);
            if (old == 63) {
                g_arrive[dir] = 0;
                __threadfence();
                atomicExch(&g_release[dir], (unsigned)(s + 1));
            } else {
                while (*((volatile unsigned*)&g_release[dir]) < (unsigned)(s + 1)) { }
            }
        }
        __syncthreads();
        __threadfence();
    }
}

// -----------------------------------------------------------------------------
// Launch
// -----------------------------------------------------------------------------
extern "C" void kernel_launch(void* const* d_in, const int* in_sizes, int n_in,
                              void* d_out, int out_size)
{
    (void)in_sizes; (void)n_in; (void)out_size;
    const float* x   = (const float*)d_in[0];
    const float* Wxf = (const float*)d_in[1];
    const float* Whf = (const float*)d_in[2];
    const float* bf  = (const float*)d_in[3];
    const float* Wxb = (const float*)d_in[4];
    const float* Whb = (const float*)d_in[5];
    const float* bb  = (const float*)d_in[6];
    float* out = (float*)d_out;

    float *xm, *hb;
    cudaGetSymbolAddress((void**)&xm, g_xm);
    cudaGetSymbolAddress((void**)&hb, g_h);

    cudaFuncSetAttribute(gru_persist_kernel,
                         cudaFuncAttributeMaxDynamicSharedMemorySize,
                         PERSIST_SMEM);

    // 1) h0 = 0, barrier state = 0
    init_kernel<<<128, 256>>>(hb);

    // 2) input projections: bf16 tensor-core GEMM, 3-pass hi/lo split
    sgemm_xm_bf16x3_kernel<<<dim3(12, 256, 2), 256>>>(x, Wxf, Wxb, bf, bb, xm);

    // 3) persistent recurrence (all 512 steps, both dirs)
    gru_persist_kernel<<<dim3(64, 2), 256, PERSIST_SMEM>>>(
        Whf, Whb, xm, hb, out);
}

// round 6
// speedup vs baseline: 1.4863x; 1.1839x over previous
#include <cuda_runtime.h>
#include <cuda_bf16.h>
#include <cstdint>

// Problem constants
#define NB   64      // batch
#define TT   512     // time steps
#define DD   512     // input dim
#define HH   512     // hidden dim
#define G3   1536    // 3*H

// Scratch (device globals: allocation-free)
__device__ float    g_xm[(size_t)2 * NB * TT * G3];     // [dir][n][t][3H]
__device__ float    g_h[2 * 2 * NB * HH];               // fp32 ping-pong
__device__ unsigned g_hbf[2 * 2 * 2 * NB * (HH / 2)];   // [dir][par][hi/lo][n][k2] bf16x2
__device__ unsigned g_arrive[2];
__device__ unsigned g_release[2];

__device__ __forceinline__ unsigned packbf(float odd_k, float even_k) {
    unsigned r;
    asm("cvt.rn.bf16x2.f32 %0, %1, %2;" : "=r"(r) : "f"(odd_k), "f"(even_k));
    return r;
}
__device__ __forceinline__ float bfres(float x) {
    return x - __bfloat162float(__float2bfloat16_rn(x));
}

__device__ __forceinline__ void mma_bf16(float* c, const unsigned* a,
                                         unsigned b0, unsigned b1) {
    asm volatile(
        "mma.sync.aligned.m16n8k16.row.col.f32.bf16.bf16.f32 "
        "{%0,%1,%2,%3}, {%4,%5,%6,%7}, {%8,%9}, {%0,%1,%2,%3};"
        : "+f"(c[0]), "+f"(c[1]), "+f"(c[2]), "+f"(c[3])
        : "r"(a[0]), "r"(a[1]), "r"(a[2]), "r"(a[3]), "r"(b0), "r"(b1));
}

// -----------------------------------------------------------------------------
// Init: zero fp32 h ping-pong + bf16 h buffers + barrier state
// -----------------------------------------------------------------------------
__global__ void init_kernel(float* h, unsigned* hbf) {
    int i = blockIdx.x * blockDim.x + threadIdx.x;   // 32768
    reinterpret_cast<float4*>(h)[i] = make_float4(0.f, 0.f, 0.f, 0.f);
    reinterpret_cast<uint4*>(hbf)[i] = make_uint4(0u, 0u, 0u, 0u);
    if (i == 0) {
        g_arrive[0] = 0; g_arrive[1] = 0;
        g_release[0] = 0; g_release[1] = 0;
    }
}

// -----------------------------------------------------------------------------
// Input projection GEMM via bf16 tensor cores, 3-pass hi/lo split (R5, proven).
// -----------------------------------------------------------------------------
#define AST 136

__global__ __launch_bounds__(256, 2) void sgemm_xm_bf16x3_kernel(
    const float* __restrict__ x,
    const float* __restrict__ Wx_f, const float* __restrict__ Wx_b,
    const float* __restrict__ b_f,  const float* __restrict__ b_b,
    float* __restrict__ xm)
{
    const int dir = blockIdx.z;
    const float* __restrict__ Wx   = dir ? Wx_b : Wx_f;
    const float* __restrict__ bias = dir ? b_b  : b_f;
    float* __restrict__ C = xm + (size_t)dir * (NB * TT) * G3;

    __shared__ __align__(16) unsigned AsH[8 * AST];
    __shared__ __align__(16) unsigned AsL[8 * AST];
    __shared__ __align__(16) unsigned BsH[8 * AST];
    __shared__ __align__(16) unsigned BsL[8 * AST];

    const int t = threadIdx.x;
    const int w = t >> 5;
    const int l = t & 31;
    const int warp_m = w >> 1;
    const int warp_n = w & 1;
    const int gid = l >> 2;
    const int tig = l & 3;

    const int mBase = blockIdx.y * 128;
    const int jBase = blockIdx.x * 128;

    const int aM  = t & 127;
    const int aKg = (t >> 7) * 8;
    const int am  = mBase + aM;
    const int an  = am >> 9;
    const int at0 = am & 511;
    const int ats = dir ? (TT - 1 - at0) : at0;
    const float* __restrict__ aPtr = x + ((size_t)an * TT + ats) * DD + aKg;
    const int aR0 = aKg >> 1;

    const int bKp = t >> 5;
    const int bN  = (t & 31) * 4;
    const float* __restrict__ bPtr = Wx + (size_t)(2 * bKp) * G3 + jBase + bN;

    float acc[2][8][4];
#pragma unroll
    for (int mt = 0; mt < 2; mt++)
#pragma unroll
        for (int nt = 0; nt < 8; nt++)
#pragma unroll
            for (int r = 0; r < 4; r++) acc[mt][nt][r] = 0.f;

    for (int k0 = 0; k0 < DD; k0 += 16) {
        {
            const float4 v0 = *reinterpret_cast<const float4*>(aPtr + k0);
            const float4 v1 = *reinterpret_cast<const float4*>(aPtr + k0 + 4);
            AsH[(aR0 + 0) * AST + aM] = packbf(v0.y, v0.x);
            AsH[(aR0 + 1) * AST + aM] = packbf(v0.w, v0.z);
            AsH[(aR0 + 2) * AST + aM] = packbf(v1.y, v1.x);
            AsH[(aR0 + 3) * AST + aM] = packbf(v1.w, v1.z);
            AsL[(aR0 + 0) * AST + aM] = packbf(bfres(v0.y), bfres(v0.x));
            AsL[(aR0 + 1) * AST + aM] = packbf(bfres(v0.w), bfres(v0.z));
            AsL[(aR0 + 2) * AST + aM] = packbf(bfres(v1.y), bfres(v1.x));
            AsL[(aR0 + 3) * AST + aM] = packbf(bfres(v1.w), bfres(v1.z));
        }
        {
            const float* p = bPtr + (size_t)k0 * G3;
            const float4 e = *reinterpret_cast<const float4*>(p);
            const float4 o = *reinterpret_cast<const float4*>(p + G3);
            uint4 hh, ll;
            hh.x = packbf(o.x, e.x); hh.y = packbf(o.y, e.y);
            hh.z = packbf(o.z, e.z); hh.w = packbf(o.w, e.w);
            ll.x = packbf(bfres(o.x), bfres(e.x));
            ll.y = packbf(bfres(o.y), bfres(e.y));
            ll.z = packbf(bfres(o.z), bfres(e.z));
            ll.w = packbf(bfres(o.w), bfres(e.w));
            *reinterpret_cast<uint4*>(&BsH[bKp * AST + bN]) = hh;
            *reinterpret_cast<uint4*>(&BsL[bKp * AST + bN]) = ll;
        }
        __syncthreads();

        unsigned ahi[2][4], alo[2][4];
#pragma unroll
        for (int mt = 0; mt < 2; mt++) {
            const int m0 = warp_m * 32 + mt * 16 + gid;
            ahi[mt][0] = AsH[tig * AST + m0];
            ahi[mt][1] = AsH[tig * AST + m0 + 8];
            ahi[mt][2] = AsH[(tig + 4) * AST + m0];
            ahi[mt][3] = AsH[(tig + 4) * AST + m0 + 8];
            alo[mt][0] = AsL[tig * AST + m0];
            alo[mt][1] = AsL[tig * AST + m0 + 8];
            alo[mt][2] = AsL[(tig + 4) * AST + m0];
            alo[mt][3] = AsL[(tig + 4) * AST + m0 + 8];
        }
#pragma unroll
        for (int nt = 0; nt < 8; nt++) {
            const int n0 = warp_n * 64 + nt * 8 + gid;
            const unsigned bh0 = BsH[tig * AST + n0];
            const unsigned bh1 = BsH[(tig + 4) * AST + n0];
            const unsigned bl0 = BsL[tig * AST + n0];
            const unsigned bl1 = BsL[(tig + 4) * AST + n0];
#pragma unroll
            for (int mt = 0; mt < 2; mt++) {
                mma_bf16(acc[mt][nt], ahi[mt], bh0, bh1);
                mma_bf16(acc[mt][nt], alo[mt], bh0, bh1);
                mma_bf16(acc[mt][nt], ahi[mt], bl0, bl1);
            }
        }
        __syncthreads();
    }

#pragma unroll
    for (int mt = 0; mt < 2; mt++) {
        const int m0 = mBase + warp_m * 32 + mt * 16 + gid;
        const int m1 = m0 + 8;
#pragma unroll
        for (int nt = 0; nt < 8; nt++) {
            const int col = jBase + warp_n * 64 + nt * 8 + tig * 2;
            const float2 bv = *reinterpret_cast<const float2*>(&bias[col]);
            float2 o0, o1;
            o0.x = acc[mt][nt][0] + bv.x;  o0.y = acc[mt][nt][1] + bv.y;
            o1.x = acc[mt][nt][2] + bv.x;  o1.y = acc[mt][nt][3] + bv.y;
            *reinterpret_cast<float2*>(&C[(size_t)m0 * G3 + col]) = o0;
            *reinterpret_cast<float2*>(&C[(size_t)m1 * G3 + col]) = o1;
        }
    }
}

// -----------------------------------------------------------------------------
// Persistent recurrence, tensor-core version.
// Grid dim3(64,2), 256 threads. Block = (dir, 8 hidden cols -> 24 gate cols).
// W_h slice pre-permuted to B-fragments in SMEM (bf16 hi/lo) once.
// h kept in GLOBAL as k-paired bf16x2 hi/lo buffers; A-fragments loaded
// directly with per-lane LDG.32 (no SMEM staging). 3 MMA passes accumulate
// into one fp32 C fragment. Split-K=2 across warp halves, 6KB SMEM exchange.
// Gates fully in-register from the C fragment lane mapping.
// -----------------------------------------------------------------------------
#define BFRAG_HALF   (32 * 3 * 64)               // uints per hi or lo = 6144
#define BFRAG_UINTS  (2 * BFRAG_HALF)            // 12288
#define REDF         (12 * 32 * 4)               // 1536 floats
#define PMMA_SMEM    ((BFRAG_UINTS + REDF) * 4)  // 55296 B

__global__ __launch_bounds__(256, 1) void gru_persist_mma_kernel(
    const float* __restrict__ Wh_f, const float* __restrict__ Wh_b,
    const float* __restrict__ xm, float* __restrict__ h32,
    unsigned* __restrict__ hbf, float* __restrict__ out)
{
    extern __shared__ unsigned smu[];
    unsigned* bfr = smu;                                  // [hl][kt][nt][lane][2]
    float* red = reinterpret_cast<float*>(smu + BFRAG_UINTS);  // [mt][nt][lane][4]

    const int dir = blockIdx.y;
    const int j0  = blockIdx.x * 8;
    const float* __restrict__ Wh = dir ? Wh_b : Wh_f;

    const int t  = threadIdx.x;
    const int w  = t >> 5;
    const int l  = t & 31;
    const int g  = l >> 2;
    const int tq = l & 3;
    const int mt = w & 3;
    const int khalf = w >> 2;

    // ---- fill W B-fragments once ----
    for (int idx = t; idx < 24 * 256; idx += 256) {
        const int c_loc = idx >> 8;          // 0..23
        const int k2    = idx & 255;
        const int gate  = c_loc >> 3;
        const int jj    = c_loc & 7;
        const int col   = gate * HH + j0 + jj;
        const float e = Wh[(size_t)(2 * k2) * G3 + col];
        const float o = Wh[(size_t)(2 * k2 + 1) * G3 + col];
        const int kt = k2 >> 3;
        const int pp = k2 & 7;
        const int rr = pp >> 2;
        const int ts = pp & 3;
        const int off = ((kt * 3 + gate) * 32 + jj * 4 + ts) * 2 + rr;
        bfr[off]              = packbf(o, e);
        bfr[BFRAG_HALF + off] = packbf(bfres(o), bfres(e));
    }
    __syncthreads();

    const int row0 = mt * 16 + g;
    const int row1 = row0 + 8;
    // gate roles (khalf==0)
    const int n0 = row0, n1 = row1;
    const int jA = j0 + 2 * tq;
    const int k2g = (j0 >> 1) + tq;
    const float* xmd = xm + (size_t)dir * (NB * TT) * G3;

    for (int s = 0; s < TT; s++) {
        const int p = s & 1;
        const float* __restrict__ hprev = h32 + ((size_t)dir * 2 + p)       * (NB * HH);
        float*       __restrict__ hnext = h32 + ((size_t)dir * 2 + (p ^ 1)) * (NB * HH);
        const unsigned* __restrict__ hbH = hbf + (((size_t)dir * 2 + p) * 2 + 0) * 16384;
        const unsigned* __restrict__ hbL = hbH + 16384;
        unsigned* __restrict__ hbHn = hbf + (((size_t)dir * 2 + (p ^ 1)) * 2 + 0) * 16384;
        unsigned* __restrict__ hbLn = hbHn + 16384;

        // ---- prefetch gate inputs (khalf0 threads only) ----
        float2 xz0, xr0, xg0, xz1, xr1, xg1, hp0, hp1;
        if (khalf == 0) {
            const float* b0 = &xmd[((size_t)n0 * TT + s) * G3 + jA];
            const float* b1 = &xmd[((size_t)n1 * TT + s) * G3 + jA];
            xz0 = __ldg((const float2*)(b0));
            xr0 = __ldg((const float2*)(b0 + HH));
            xg0 = __ldg((const float2*)(b0 + 2 * HH));
            xz1 = __ldg((const float2*)(b1));
            xr1 = __ldg((const float2*)(b1 + HH));
            xg1 = __ldg((const float2*)(b1 + 2 * HH));
            hp0 = __ldg((const float2*)&hprev[n0 * HH + jA]);
            hp1 = __ldg((const float2*)&hprev[n1 * HH + jA]);
        }

        // ---- MMA mainloop: A fragments direct from global bf16 h ----
        float acc[3][4];
#pragma unroll
        for (int nt = 0; nt < 3; nt++)
#pragma unroll
            for (int r = 0; r < 4; r++) acc[nt][r] = 0.f;

        const int ktb = khalf * 16;
        unsigned aH[2][4], aL[2][4];
        {
            const int kb = ktb * 8 + tq;
            aH[0][0] = __ldg(&hbH[row0 * 256 + kb]);
            aH[0][1] = __ldg(&hbH[row1 * 256 + kb]);
            aH[0][2] = __ldg(&hbH[row0 * 256 + kb + 4]);
            aH[0][3] = __ldg(&hbH[row1 * 256 + kb + 4]);
            aL[0][0] = __ldg(&hbL[row0 * 256 + kb]);
            aL[0][1] = __ldg(&hbL[row1 * 256 + kb]);
            aL[0][2] = __ldg(&hbL[row0 * 256 + kb + 4]);
            aL[0][3] = __ldg(&hbL[row1 * 256 + kb + 4]);
        }
#pragma unroll
        for (int ki = 0; ki < 16; ki++) {
            const int kt  = ktb + ki;
            const int cur = ki & 1;
            if (ki < 15) {
                const int kb = (kt + 1) * 8 + tq;
                aH[cur ^ 1][0] = __ldg(&hbH[row0 * 256 + kb]);
                aH[cur ^ 1][1] = __ldg(&hbH[row1 * 256 + kb]);
                aH[cur ^ 1][2] = __ldg(&hbH[row0 * 256 + kb + 4]);
                aH[cur ^ 1][3] = __ldg(&hbH[row1 * 256 + kb + 4]);
                aL[cur ^ 1][0] = __ldg(&hbL[row0 * 256 + kb]);
                aL[cur ^ 1][1] = __ldg(&hbL[row1 * 256 + kb]);
                aL[cur ^ 1][2] = __ldg(&hbL[row0 * 256 + kb + 4]);
                aL[cur ^ 1][3] = __ldg(&hbL[row1 * 256 + kb + 4]);
            }
#pragma unroll
            for (int nt = 0; nt < 3; nt++) {
                const int off = ((kt * 3 + nt) * 32 + l) * 2;
                const uint2 bh = *reinterpret_cast<const uint2*>(&bfr[off]);
                const uint2 bl = *reinterpret_cast<const uint2*>(&bfr[BFRAG_HALF + off]);
                mma_bf16(acc[nt], aH[cur], bh.x, bh.y);
                mma_bf16(acc[nt], aL[cur], bh.x, bh.y);
                mma_bf16(acc[nt], aH[cur], bl.x, bl.y);
            }
        }

        // ---- split-K exchange ----
        if (khalf == 1) {
#pragma unroll
            for (int nt = 0; nt < 3; nt++) {
                float4 v = make_float4(acc[nt][0], acc[nt][1], acc[nt][2], acc[nt][3]);
                *reinterpret_cast<float4*>(&red[((mt * 3 + nt) * 32 + l) * 4]) = v;
            }
        }
        __syncthreads();

        if (khalf == 0) {
#pragma unroll
            for (int nt = 0; nt < 3; nt++) {
                const float4 v = *reinterpret_cast<const float4*>(
                    &red[((mt * 3 + nt) * 32 + l) * 4]);
                acc[nt][0] += v.x; acc[nt][1] += v.y;
                acc[nt][2] += v.z; acc[nt][3] += v.w;
            }
            // gates, fully in-register:
            // q0=(n0,jA) q1=(n0,jB) q2=(n1,jA) q3=(n1,jB)
            const float z0a = 1.f / (1.f + __expf(-(xz0.x + acc[0][0])));
            const float z0b = 1.f / (1.f + __expf(-(xz0.y + acc[0][1])));
            const float z1a = 1.f / (1.f + __expf(-(xz1.x + acc[0][2])));
            const float z1b = 1.f / (1.f + __expf(-(xz1.y + acc[0][3])));
            const float r0a = 1.f / (1.f + __expf(-(xr0.x + acc[1][0])));
            const float r0b = 1.f / (1.f + __expf(-(xr0.y + acc[1][1])));
            const float r1a = 1.f / (1.f + __expf(-(xr1.x + acc[1][2])));
            const float r1b = 1.f / (1.f + __expf(-(xr1.y + acc[1][3])));
            const float g0a = tanhf(xg0.x + r0a * acc[2][0]);
            const float g0b = tanhf(xg0.y + r0b * acc[2][1]);
            const float g1a = tanhf(xg1.x + r1a * acc[2][2]);
            const float g1b = tanhf(xg1.y + r1b * acc[2][3]);
            const float h0a = (1.f - z0a) * g0a + z0a * hp0.x;
            const float h0b = (1.f - z0b) * g0b + z0b * hp0.y;
            const float h1a = (1.f - z1a) * g1a + z1a * hp1.x;
            const float h1b = (1.f - z1b) * g1b + z1b * hp1.y;

            *reinterpret_cast<float2*>(&hnext[n0 * HH + jA]) = make_float2(h0a, h0b);
            *reinterpret_cast<float2*>(&hnext[n1 * HH + jA]) = make_float2(h1a, h1b);
            const int t_out = dir ? (TT - 1 - s) : s;
            *reinterpret_cast<float2*>(
                &out[((size_t)n0 * TT + t_out) * (2 * HH) + dir * HH + jA]) =
                make_float2(h0a, h0b);
            *reinterpret_cast<float2*>(
                &out[((size_t)n1 * TT + t_out) * (2 * HH) + dir * HH + jA]) =
                make_float2(h1a, h1b);
            hbHn[n0 * 256 + k2g] = packbf(h0b, h0a);
            hbLn[n0 * 256 + k2g] = packbf(bfres(h0b), bfres(h0a));
            hbHn[n1 * 256 + k2g] = packbf(h1b, h1a);
            hbLn[n1 * 256 + k2g] = packbf(bfres(h1b), bfres(h1a));
        }

        // ---- per-direction grid barrier (64 blocks) ----
        __syncthreads();
        __threadfence();
        if (t == 0) {
            const unsigned old = atomicAdd(&g_arrive[dir], 1);
            if (old == 63) {
                g_arrive[dir] = 0;
                __threadfence();
                atomicExch(&g_release[dir], (unsigned)(s + 1));
            } else {
                while (*((volatile unsigned*)&g_release[dir]) < (unsigned)(s + 1)) { }
            }
        }
        __syncthreads();
        __threadfence();
    }
}

// -----------------------------------------------------------------------------
// Launch
// -----------------------------------------------------------------------------
extern "C" void kernel_launch(void* const* d_in, const int* in_sizes, int n_in,
                              void* d_out, int out_size)
{
    (void)in_sizes; (void)n_in; (void)out_size;
    const float* x   = (const float*)d_in[0];
    const float* Wxf = (const float*)d_in[1];
    const float* Whf = (const float*)d_in[2];
    const float* bf  = (const float*)d_in[3];
    const float* Wxb = (const float*)d_in[4];
    const float* Whb = (const float*)d_in[5];
    const float* bb  = (const float*)d_in[6];
    float* out = (float*)d_out;

    float *xm, *hb;
    unsigned* hbf;
    cudaGetSymbolAddress((void**)&xm, g_xm);
    cudaGetSymbolAddress((void**)&hb, g_h);
    cudaGetSymbolAddress((void**)&hbf, g_hbf);

    cudaFuncSetAttribute(gru_persist_mma_kernel,
                         cudaFuncAttributeMaxDynamicSharedMemorySize,
                         PMMA_SMEM);

    // 1) h0 = 0 (fp32 + bf16 buffers), barrier state = 0
    init_kernel<<<128, 256>>>(hb, hbf);

    // 2) input projections: bf16 tensor-core GEMM, 3-pass hi/lo split
    sgemm_xm_bf16x3_kernel<<<dim3(12, 256, 2), 256>>>(x, Wxf, Wxb, bf, bb, xm);

    // 3) persistent recurrence, tensor-core steps
    gru_persist_mma_kernel<<<dim3(64, 2), 256, PMMA_SMEM>>>(
        Whf, Whb, xm, hb, hbf, out);
}

// round 7
// speedup vs baseline: 1.9572x; 1.3168x over previous
#include <cuda_runtime.h>
#include <cuda_bf16.h>
#include <cstdint>

// Problem constants
#define NB   64      // batch
#define TT   512     // time steps
#define DD   512     // input dim
#define HH   512     // hidden dim
#define G3   1536    // 3*H

// Scratch (device globals: allocation-free)
__device__ float    g_xm[(size_t)2 * NB * TT * G3];   // [dir][n][t][3H]
__device__ float    g_h[2 * 2 * NB * HH];             // fp32 ping-pong
// bf16 h, fragment-ready layout: [dir][par][row(64)][kt(32)][tq(4)][4]
//   cell = { hi(k2=kt*8+tq), lo(same), hi(k2=kt*8+tq+4), lo(same) }
__device__ unsigned g_hbf[2 * 2 * 64 * 512];
__device__ unsigned g_arrive[2];
__device__ unsigned g_release[2];

__device__ __forceinline__ unsigned packbf(float odd_k, float even_k) {
    unsigned r;
    asm("cvt.rn.bf16x2.f32 %0, %1, %2;" : "=r"(r) : "f"(odd_k), "f"(even_k));
    return r;
}
__device__ __forceinline__ float bfres(float x) {
    return x - __bfloat162float(__float2bfloat16_rn(x));
}

__device__ __forceinline__ void mma_bf16(float* c, const unsigned* a,
                                         unsigned b0, unsigned b1) {
    asm volatile(
        "mma.sync.aligned.m16n8k16.row.col.f32.bf16.bf16.f32 "
        "{%0,%1,%2,%3}, {%4,%5,%6,%7}, {%8,%9}, {%0,%1,%2,%3};"
        : "+f"(c[0]), "+f"(c[1]), "+f"(c[2]), "+f"(c[3])
        : "r"(a[0]), "r"(a[1]), "r"(a[2]), "r"(a[3]), "r"(b0), "r"(b1));
}

// -----------------------------------------------------------------------------
// Init: zero fp32 h ping-pong + bf16 h buffers + barrier state
// -----------------------------------------------------------------------------
__global__ void init_kernel(float* h, unsigned* hbf) {
    int i = blockIdx.x * blockDim.x + threadIdx.x;   // 32768
    reinterpret_cast<float4*>(h)[i] = make_float4(0.f, 0.f, 0.f, 0.f);
    reinterpret_cast<uint4*>(hbf)[i] = make_uint4(0u, 0u, 0u, 0u);
    if (i == 0) {
        g_arrive[0] = 0; g_arrive[1] = 0;
        g_release[0] = 0; g_release[1] = 0;
    }
}

// -----------------------------------------------------------------------------
// Input projection GEMM via bf16 tensor cores, 3-pass hi/lo split,
// now with register-prefetch software pipeline (LDG of tile k+1 overlapped
// with MMA of tile k).
// -----------------------------------------------------------------------------
#define AST 136

__global__ __launch_bounds__(256, 2) void sgemm_xm_bf16x3_kernel(
    const float* __restrict__ x,
    const float* __restrict__ Wx_f, const float* __restrict__ Wx_b,
    const float* __restrict__ b_f,  const float* __restrict__ b_b,
    float* __restrict__ xm)
{
    const int dir = blockIdx.z;
    const float* __restrict__ Wx   = dir ? Wx_b : Wx_f;
    const float* __restrict__ bias = dir ? b_b  : b_f;
    float* __restrict__ C = xm + (size_t)dir * (NB * TT) * G3;

    __shared__ __align__(16) unsigned AsH[8 * AST];
    __shared__ __align__(16) unsigned AsL[8 * AST];
    __shared__ __align__(16) unsigned BsH[8 * AST];
    __shared__ __align__(16) unsigned BsL[8 * AST];

    const int t = threadIdx.x;
    const int w = t >> 5;
    const int l = t & 31;
    const int warp_m = w >> 1;
    const int warp_n = w & 1;
    const int gid = l >> 2;
    const int tig = l & 3;

    const int mBase = blockIdx.y * 128;
    const int jBase = blockIdx.x * 128;

    const int aM  = t & 127;
    const int aKg = (t >> 7) * 8;
    const int am  = mBase + aM;
    const int an  = am >> 9;
    const int at0 = am & 511;
    const int ats = dir ? (TT - 1 - at0) : at0;
    const float* __restrict__ aPtr = x + ((size_t)an * TT + ats) * DD + aKg;
    const int aR0 = aKg >> 1;

    const int bKp = t >> 5;
    const int bN  = (t & 31) * 4;
    const float* __restrict__ bPtr = Wx + (size_t)(2 * bKp) * G3 + jBase + bN;

    float acc[2][8][4];
#pragma unroll
    for (int mt = 0; mt < 2; mt++)
#pragma unroll
        for (int nt = 0; nt < 8; nt++)
#pragma unroll
            for (int r = 0; r < 4; r++) acc[mt][nt][r] = 0.f;

    // ---- prologue: prefetch tile 0 into registers ----
    float4 av0 = *reinterpret_cast<const float4*>(aPtr);
    float4 av1 = *reinterpret_cast<const float4*>(aPtr + 4);
    float4 be  = *reinterpret_cast<const float4*>(bPtr);
    float4 bo  = *reinterpret_cast<const float4*>(bPtr + G3);

    for (int k0 = 0; k0 < DD; k0 += 16) {
        // ---- STS from registers ----
        AsH[(aR0 + 0) * AST + aM] = packbf(av0.y, av0.x);
        AsH[(aR0 + 1) * AST + aM] = packbf(av0.w, av0.z);
        AsH[(aR0 + 2) * AST + aM] = packbf(av1.y, av1.x);
        AsH[(aR0 + 3) * AST + aM] = packbf(av1.w, av1.z);
        AsL[(aR0 + 0) * AST + aM] = packbf(bfres(av0.y), bfres(av0.x));
        AsL[(aR0 + 1) * AST + aM] = packbf(bfres(av0.w), bfres(av0.z));
        AsL[(aR0 + 2) * AST + aM] = packbf(bfres(av1.y), bfres(av1.x));
        AsL[(aR0 + 3) * AST + aM] = packbf(bfres(av1.w), bfres(av1.z));
        {
            uint4 hh, ll;
            hh.x = packbf(bo.x, be.x); hh.y = packbf(bo.y, be.y);
            hh.z = packbf(bo.z, be.z); hh.w = packbf(bo.w, be.w);
            ll.x = packbf(bfres(bo.x), bfres(be.x));
            ll.y = packbf(bfres(bo.y), bfres(be.y));
            ll.z = packbf(bfres(bo.z), bfres(be.z));
            ll.w = packbf(bfres(bo.w), bfres(be.w));
            *reinterpret_cast<uint4*>(&BsH[bKp * AST + bN]) = hh;
            *reinterpret_cast<uint4*>(&BsL[bKp * AST + bN]) = ll;
        }
        __syncthreads();

        // ---- prefetch next tile (overlaps with MMA below) ----
        if (k0 + 16 < DD) {
            av0 = *reinterpret_cast<const float4*>(aPtr + k0 + 16);
            av1 = *reinterpret_cast<const float4*>(aPtr + k0 + 20);
            be  = *reinterpret_cast<const float4*>(bPtr + (size_t)(k0 + 16) * G3);
            bo  = *reinterpret_cast<const float4*>(bPtr + (size_t)(k0 + 16) * G3 + G3);
        }

        // ---- fragment loads + MMAs ----
        unsigned ahi[2][4], alo[2][4];
#pragma unroll
        for (int mt = 0; mt < 2; mt++) {
            const int m0 = warp_m * 32 + mt * 16 + gid;
            ahi[mt][0] = AsH[tig * AST + m0];
            ahi[mt][1] = AsH[tig * AST + m0 + 8];
            ahi[mt][2] = AsH[(tig + 4) * AST + m0];
            ahi[mt][3] = AsH[(tig + 4) * AST + m0 + 8];
            alo[mt][0] = AsL[tig * AST + m0];
            alo[mt][1] = AsL[tig * AST + m0 + 8];
            alo[mt][2] = AsL[(tig + 4) * AST + m0];
            alo[mt][3] = AsL[(tig + 4) * AST + m0 + 8];
        }
#pragma unroll
        for (int nt = 0; nt < 8; nt++) {
            const int n0 = warp_n * 64 + nt * 8 + gid;
            const unsigned bh0 = BsH[tig * AST + n0];
            const unsigned bh1 = BsH[(tig + 4) * AST + n0];
            const unsigned bl0 = BsL[tig * AST + n0];
            const unsigned bl1 = BsL[(tig + 4) * AST + n0];
#pragma unroll
            for (int mt = 0; mt < 2; mt++) {
                mma_bf16(acc[mt][nt], ahi[mt], bh0, bh1);
                mma_bf16(acc[mt][nt], alo[mt], bh0, bh1);
                mma_bf16(acc[mt][nt], ahi[mt], bl0, bl1);
            }
        }
        __syncthreads();
    }

#pragma unroll
    for (int mt = 0; mt < 2; mt++) {
        const int m0 = mBase + warp_m * 32 + mt * 16 + gid;
        const int m1 = m0 + 8;
#pragma unroll
        for (int nt = 0; nt < 8; nt++) {
            const int col = jBase + warp_n * 64 + nt * 8 + tig * 2;
            const float2 bv = *reinterpret_cast<const float2*>(&bias[col]);
            float2 o0, o1;
            o0.x = acc[mt][nt][0] + bv.x;  o0.y = acc[mt][nt][1] + bv.y;
            o1.x = acc[mt][nt][2] + bv.x;  o1.y = acc[mt][nt][3] + bv.y;
            *reinterpret_cast<float2*>(&C[(size_t)m0 * G3 + col]) = o0;
            *reinterpret_cast<float2*>(&C[(size_t)m1 * G3 + col]) = o1;
        }
    }
}

// -----------------------------------------------------------------------------
// Persistent recurrence, tensor-core version with wide fragment loads.
// Per ki: 2 LDG.128 (A hi+lo, both rows) + 3 LDS.128 (B hi+lo) + 9 MMA.
// -----------------------------------------------------------------------------
#define BFRAG_UINTS  (32 * 3 * 32 * 4)           // 12288 (48KB)
#define REDF         (12 * 32 * 4)               // 1536 floats
#define PMMA_SMEM    ((BFRAG_UINTS + REDF) * 4)  // 55296 B
#define HB_PP        32768                       // uints per (dir,parity)

__global__ __launch_bounds__(256, 1) void gru_persist_mma_kernel(
    const float* __restrict__ Wh_f, const float* __restrict__ Wh_b,
    const float* __restrict__ xm, float* __restrict__ h32,
    unsigned* __restrict__ hbf, float* __restrict__ out)
{
    extern __shared__ unsigned smu[];
    unsigned* bfr = smu;                          // [kt][nt][lane][4] = bh0,bh1,bl0,bl1
    float* red = reinterpret_cast<float*>(smu + BFRAG_UINTS);

    const int dir = blockIdx.y;
    const int j0  = blockIdx.x * 8;
    const float* __restrict__ Wh = dir ? Wh_b : Wh_f;

    const int t  = threadIdx.x;
    const int w  = t >> 5;
    const int l  = t & 31;
    const int g  = l >> 2;
    const int tq = l & 3;
    const int mt = w & 3;
    const int khalf = w >> 2;

    // ---- fill W B-fragments once: [kt][gate][lane(col*4+ts)][bh0,bh1,bl0,bl1] ----
    for (int idx = t; idx < 24 * 256; idx += 256) {
        const int c_loc = idx >> 8;          // 0..23
        const int k2    = idx & 255;
        const int gate  = c_loc >> 3;
        const int jj    = c_loc & 7;
        const int col   = gate * HH + j0 + jj;
        const float e = Wh[(size_t)(2 * k2) * G3 + col];
        const float o = Wh[(size_t)(2 * k2 + 1) * G3 + col];
        const int kt = k2 >> 3;
        const int pp = k2 & 7;
        const int rr = pp >> 2;              // b reg index (0/1)
        const int ts = pp & 3;
        const int off4 = ((kt * 3 + gate) * 32 + jj * 4 + ts) * 4;
        bfr[off4 + rr]     = packbf(o, e);
        bfr[off4 + 2 + rr] = packbf(bfres(o), bfres(e));
    }
    __syncthreads();

    const int row0 = mt * 16 + g;
    const int row1 = row0 + 8;
    const int n0 = row0, n1 = row1;
    const int jA  = j0 + 2 * tq;
    const int k2g = (j0 >> 1) + tq;
    // writer cell coords for k2g
    const int wkt = k2g >> 3;
    const int wpp = k2g & 7;
    const int wtq = wpp & 3;
    const int wsl = (wpp >> 2) * 2;          // 0 or 2
    const float* xmd = xm + (size_t)dir * (NB * TT) * G3;

    for (int s = 0; s < TT; s++) {
        const int p = s & 1;
        const float* __restrict__ hprev = h32 + ((size_t)dir * 2 + p)       * (NB * HH);
        float*       __restrict__ hnext = h32 + ((size_t)dir * 2 + (p ^ 1)) * (NB * HH);
        const unsigned* __restrict__ hb  = hbf + ((size_t)dir * 2 + p)       * HB_PP;
        unsigned*       __restrict__ hbn = hbf + ((size_t)dir * 2 + (p ^ 1)) * HB_PP;

        // ---- prefetch gate inputs (khalf0 threads only) ----
        float2 xz0, xr0, xg0, xz1, xr1, xg1, hp0, hp1;
        if (khalf == 0) {
            const float* b0 = &xmd[((size_t)n0 * TT + s) * G3 + jA];
            const float* b1 = &xmd[((size_t)n1 * TT + s) * G3 + jA];
            xz0 = __ldg((const float2*)(b0));
            xr0 = __ldg((const float2*)(b0 + HH));
            xg0 = __ldg((const float2*)(b0 + 2 * HH));
            xz1 = __ldg((const float2*)(b1));
            xr1 = __ldg((const float2*)(b1 + HH));
            xg1 = __ldg((const float2*)(b1 + 2 * HH));
            hp0 = __ldg((const float2*)&hprev[n0 * HH + jA]);
            hp1 = __ldg((const float2*)&hprev[n1 * HH + jA]);
        }

        // ---- MMA mainloop ----
        float acc[3][4];
#pragma unroll
        for (int nt = 0; nt < 3; nt++)
#pragma unroll
            for (int r = 0; r < 4; r++) acc[nt][r] = 0.f;

        const int ktb = khalf * 16;
        uint4 v0[2], v1[2];
        {
            const int a = row0 * 512 + ktb * 16 + tq * 4;
            const int b = row1 * 512 + ktb * 16 + tq * 4;
            v0[0] = __ldg(reinterpret_cast<const uint4*>(&hb[a]));
            v1[0] = __ldg(reinterpret_cast<const uint4*>(&hb[b]));
        }
#pragma unroll
        for (int ki = 0; ki < 16; ki++) {
            const int kt  = ktb + ki;
            const int cur = ki & 1;
            if (ki < 15) {
                const int a = row0 * 512 + (kt + 1) * 16 + tq * 4;
                const int b = row1 * 512 + (kt + 1) * 16 + tq * 4;
                v0[cur ^ 1] = __ldg(reinterpret_cast<const uint4*>(&hb[a]));
                v1[cur ^ 1] = __ldg(reinterpret_cast<const uint4*>(&hb[b]));
            }
            unsigned aH[4], aL[4];
            aH[0] = v0[cur].x; aH[1] = v1[cur].x; aH[2] = v0[cur].z; aH[3] = v1[cur].z;
            aL[0] = v0[cur].y; aL[1] = v1[cur].y; aL[2] = v0[cur].w; aL[3] = v1[cur].w;
#pragma unroll
            for (int nt = 0; nt < 3; nt++) {
                const uint4 bb = *reinterpret_cast<const uint4*>(
                    &bfr[((kt * 3 + nt) * 32 + l) * 4]);
                mma_bf16(acc[nt], aH, bb.x, bb.y);
                mma_bf16(acc[nt], aL, bb.x, bb.y);
                mma_bf16(acc[nt], aH, bb.z, bb.w);
            }
        }

        // ---- split-K exchange ----
        if (khalf == 1) {
#pragma unroll
            for (int nt = 0; nt < 3; nt++) {
                float4 v = make_float4(acc[nt][0], acc[nt][1], acc[nt][2], acc[nt][3]);
                *reinterpret_cast<float4*>(&red[((mt * 3 + nt) * 32 + l) * 4]) = v;
            }
        }
        __syncthreads();

        if (khalf == 0) {
#pragma unroll
            for (int nt = 0; nt < 3; nt++) {
                const float4 v = *reinterpret_cast<const float4*>(
                    &red[((mt * 3 + nt) * 32 + l) * 4]);
                acc[nt][0] += v.x; acc[nt][1] += v.y;
                acc[nt][2] += v.z; acc[nt][3] += v.w;
            }
            const float z0a = 1.f / (1.f + __expf(-(xz0.x + acc[0][0])));
            const float z0b = 1.f / (1.f + __expf(-(xz0.y + acc[0][1])));
            const float z1a = 1.f / (1.f + __expf(-(xz1.x + acc[0][2])));
            const float z1b = 1.f / (1.f + __expf(-(xz1.y + acc[0][3])));
            const float r0a = 1.f / (1.f + __expf(-(xr0.x + acc[1][0])));
            const float r0b = 1.f / (1.f + __expf(-(xr0.y + acc[1][1])));
            const float r1a = 1.f / (1.f + __expf(-(xr1.x + acc[1][2])));
            const float r1b = 1.f / (1.f + __expf(-(xr1.y + acc[1][3])));
            const float g0a = tanhf(xg0.x + r0a * acc[2][0]);
            const float g0b = tanhf(xg0.y + r0b * acc[2][1]);
            const float g1a = tanhf(xg1.x + r1a * acc[2][2]);
            const float g1b = tanhf(xg1.y + r1b * acc[2][3]);
            const float h0a = (1.f - z0a) * g0a + z0a * hp0.x;
            const float h0b = (1.f - z0b) * g0b + z0b * hp0.y;
            const float h1a = (1.f - z1a) * g1a + z1a * hp1.x;
            const float h1b = (1.f - z1b) * g1b + z1b * hp1.y;

            *reinterpret_cast<float2*>(&hnext[n0 * HH + jA]) = make_float2(h0a, h0b);
            *reinterpret_cast<float2*>(&hnext[n1 * HH + jA]) = make_float2(h1a, h1b);
            const int t_out = dir ? (TT - 1 - s) : s;
            *reinterpret_cast<float2*>(
                &out[((size_t)n0 * TT + t_out) * (2 * HH) + dir * HH + jA]) =
                make_float2(h0a, h0b);
            *reinterpret_cast<float2*>(
                &out[((size_t)n1 * TT + t_out) * (2 * HH) + dir * HH + jA]) =
                make_float2(h1a, h1b);
            // bf16 fragment-layout writes (hi,lo pairs -> STG.64)
            *reinterpret_cast<uint2*>(&hbn[n0 * 512 + wkt * 16 + wtq * 4 + wsl]) =
                make_uint2(packbf(h0b, h0a), packbf(bfres(h0b), bfres(h0a)));
            *reinterpret_cast<uint2*>(&hbn[n1 * 512 + wkt * 16 + wtq * 4 + wsl]) =
                make_uint2(packbf(h1b, h1a), packbf(bfres(h1b), bfres(h1a)));
        }

        // ---- per-direction grid barrier (64 blocks) ----
        __syncthreads();
        __threadfence();
        if (t == 0) {
            const unsigned old = atomicAdd(&g_arrive[dir], 1);
            if (old == 63) {
                g_arrive[dir] = 0;
                __threadfence();
                atomicExch(&g_release[dir], (unsigned)(s + 1));
            } else {
                while (*((volatile unsigned*)&g_release[dir]) < (unsigned)(s + 1)) { }
            }
        }
        __syncthreads();
        __threadfence();
    }
}

// -----------------------------------------------------------------------------
// Launch
// -----------------------------------------------------------------------------
extern "C" void kernel_launch(void* const* d_in, const int* in_sizes, int n_in,
                              void* d_out, int out_size)
{
    (void)in_sizes; (void)n_in; (void)out_size;
    const float* x   = (const float*)d_in[0];
    const float* Wxf = (const float*)d_in[1];
    const float* Whf = (const float*)d_in[2];
    const float* bf  = (const float*)d_in[3];
    const float* Wxb = (const float*)d_in[4];
    const float* Whb = (const float*)d_in[5];
    const float* bb  = (const float*)d_in[6];
    float* out = (float*)d_out;

    float *xm, *hb;
    unsigned* hbf;
    cudaGetSymbolAddress((void**)&xm, g_xm);
    cudaGetSymbolAddress((void**)&hb, g_h);
    cudaGetSymbolAddress((void**)&hbf, g_hbf);

    cudaFuncSetAttribute(gru_persist_mma_kernel,
                         cudaFuncAttributeMaxDynamicSharedMemorySize,
                         PMMA_SMEM);

    // 1) h0 = 0 (fp32 + bf16 buffers), barrier state = 0
    init_kernel<<<128, 256>>>(hb, hbf);

    // 2) input projections: bf16 tensor-core GEMM, pipelined
    sgemm_xm_bf16x3_kernel<<<dim3(12, 256, 2), 256>>>(x, Wxf, Wxb, bf, bb, xm);

    // 3) persistent recurrence, tensor-core steps
    gru_persist_mma_kernel<<<dim3(64, 2), 256, PMMA_SMEM>>>(
        Whf, Whb, xm, hb, hbf, out);
}

// round 8
// speedup vs baseline: 2.1782x; 1.1129x over previous
#include <cuda_runtime.h>
#include <cuda_bf16.h>
#include <cstdint>

// Problem constants
#define NB   64      // batch
#define TT   512     // time steps
#define DD   512     // input dim
#define HH   512     // hidden dim
#define G3   1536    // 3*H

// Scratch (device globals: allocation-free)
__device__ float    g_xm[(size_t)2 * NB * TT * G3];   // [dir][n][t][3H]
// bf16 h, fragment-ready layout: [dir][par][row(64)][kt(32)][tq(4)][4]
__device__ unsigned g_hbf[2 * 2 * 64 * 512];
__device__ unsigned g_arrive[2];                      // monotonic barrier counters

__device__ __forceinline__ unsigned packbf(float odd_k, float even_k) {
    unsigned r;
    asm("cvt.rn.bf16x2.f32 %0, %1, %2;" : "=r"(r) : "f"(odd_k), "f"(even_k));
    return r;
}
__device__ __forceinline__ float bfres(float x) {
    return x - __bfloat162float(__float2bfloat16_rn(x));
}
__device__ __forceinline__ void mma_bf16(float* c, const unsigned* a,
                                         unsigned b0, unsigned b1) {
    asm volatile(
        "mma.sync.aligned.m16n8k16.row.col.f32.bf16.bf16.f32 "
        "{%0,%1,%2,%3}, {%4,%5,%6,%7}, {%8,%9}, {%0,%1,%2,%3};"
        : "+f"(c[0]), "+f"(c[1]), "+f"(c[2]), "+f"(c[3])
        : "r"(a[0]), "r"(a[1]), "r"(a[2]), "r"(a[3]), "r"(b0), "r"(b1));
}
__device__ __forceinline__ void ldsm_x4(unsigned& r0, unsigned& r1,
                                        unsigned& r2, unsigned& r3, unsigned sa) {
    asm volatile("ldmatrix.sync.aligned.m8n8.x4.shared.b16 {%0,%1,%2,%3}, [%4];"
                 : "=r"(r0), "=r"(r1), "=r"(r2), "=r"(r3) : "r"(sa));
}
__device__ __forceinline__ unsigned sm32(const void* p) {
    return (unsigned)__cvta_generic_to_shared(p);
}

// -----------------------------------------------------------------------------
// Init: zero bf16 h buffers + barrier counters
// -----------------------------------------------------------------------------
__global__ void init_kernel(unsigned* hbf) {
    int i = blockIdx.x * blockDim.x + threadIdx.x;   // 32768 uint4s = 131072 uints
    reinterpret_cast<uint4*>(hbf)[i] = make_uint4(0u, 0u, 0u, 0u);
    if (i == 0) { g_arrive[0] = 0; g_arrive[1] = 0; }
}

// -----------------------------------------------------------------------------
// Input projection GEMM: bf16 MMA, 3-pass hi/lo split, ldmatrix fragment loads.
// SMEM tiles: row-major, k-consecutive bf16x2, row stride 12 uints (48B —
// LDSM-conflict-free since {12r mod 32} spans disjoint 4-bank groups).
// Per warp per k-tile: 12 LDSM.x4 + 48 MMA. Register-prefetch pipeline.
// Grid: (12, 256, 2).
// -----------------------------------------------------------------------------
#define ARS 12

__global__ __launch_bounds__(256, 2) void sgemm_xm_bf16x3_kernel(
    const float* __restrict__ x,
    const float* __restrict__ Wx_f, const float* __restrict__ Wx_b,
    const float* __restrict__ b_f,  const float* __restrict__ b_b,
    float* __restrict__ xm)
{
    const int dir = blockIdx.z;
    const float* __restrict__ Wx   = dir ? Wx_b : Wx_f;
    const float* __restrict__ bias = dir ? b_b  : b_f;
    float* __restrict__ C = xm + (size_t)dir * (NB * TT) * G3;

    __shared__ __align__(16) unsigned AH[128 * ARS];
    __shared__ __align__(16) unsigned AL[128 * ARS];
    __shared__ __align__(16) unsigned BH[128 * ARS];
    __shared__ __align__(16) unsigned BL[128 * ARS];

    const int t = threadIdx.x;
    const int w = t >> 5;
    const int l = t & 31;
    const int warp_m = w >> 1;
    const int warp_n = w & 1;
    const int gid = l >> 2;
    const int tig = l & 3;

    const int mBase = blockIdx.y * 128;
    const int jBase = blockIdx.x * 128;

    // ---- A staging role: row aM, k-octet ----
    const int aM  = t & 127;
    const int aKg = (t >> 7) * 8;          // 0 or 8
    const int am  = mBase + aM;
    const int an  = am >> 9;
    const int at0 = am & 511;
    const int ats = dir ? (TT - 1 - at0) : at0;
    const float* __restrict__ aPtr = x + ((size_t)an * TT + ats) * DD + aKg;
    const int aCol = aKg >> 1;             // uint offset 0 or 4

    // ---- B staging role: k-pair = t&7, n quad = (t>>3)*4 ----
    const int bKp = t & 7;
    const int bN  = (t >> 3) * 4;
    const float* __restrict__ bPtr = Wx + (size_t)(2 * bKp) * G3 + jBase + bN;

    // ---- ldmatrix lane addresses (fixed per thread) ----
    unsigned aAdH[2], aAdL[2], bAdH[4], bAdL[4];
    {
        const int rowA = warp_m * 32 + (l & 7) + 8 * ((l >> 3) & 1);
        const int chA  = l >> 4;
#pragma unroll
        for (int mt = 0; mt < 2; mt++) {
            const int r = rowA + mt * 16;
            aAdH[mt] = sm32(&AH[r * ARS + chA * 4]);
            aAdL[mt] = sm32(&AL[r * ARS + chA * 4]);
        }
        const int rowB = warp_n * 64 + (l & 7) + 8 * ((l >> 4) & 1);
        const int chB  = (l >> 3) & 1;
#pragma unroll
        for (int np = 0; np < 4; np++) {
            const int n = rowB + np * 16;
            bAdH[np] = sm32(&BH[n * ARS + chB * 4]);
            bAdL[np] = sm32(&BL[n * ARS + chB * 4]);
        }
    }

    float acc[2][8][4];
#pragma unroll
    for (int mt = 0; mt < 2; mt++)
#pragma unroll
        for (int nt = 0; nt < 8; nt++)
#pragma unroll
            for (int r = 0; r < 4; r++) acc[mt][nt][r] = 0.f;

    // ---- prologue prefetch ----
    float4 av0 = *reinterpret_cast<const float4*>(aPtr);
    float4 av1 = *reinterpret_cast<const float4*>(aPtr + 4);
    float4 be  = *reinterpret_cast<const float4*>(bPtr);
    float4 bo  = *reinterpret_cast<const float4*>(bPtr + G3);

    for (int k0 = 0; k0 < DD; k0 += 16) {
        // ---- stage A (2x STS.128), k-consecutive pairs ----
        {
            uint4 hh, ll;
            hh.x = packbf(av0.y, av0.x); hh.y = packbf(av0.w, av0.z);
            hh.z = packbf(av1.y, av1.x); hh.w = packbf(av1.w, av1.z);
            ll.x = packbf(bfres(av0.y), bfres(av0.x));
            ll.y = packbf(bfres(av0.w), bfres(av0.z));
            ll.z = packbf(bfres(av1.y), bfres(av1.x));
            ll.w = packbf(bfres(av1.w), bfres(av1.z));
            *reinterpret_cast<uint4*>(&AH[aM * ARS + aCol]) = hh;
            *reinterpret_cast<uint4*>(&AL[aM * ARS + aCol]) = ll;
        }
        // ---- stage B: 4 n-rows, one k-pair each ----
        {
            const float ee[4] = {be.x, be.y, be.z, be.w};
            const float oo[4] = {bo.x, bo.y, bo.z, bo.w};
#pragma unroll
            for (int c = 0; c < 4; c++) {
                BH[(bN + c) * ARS + bKp] = packbf(oo[c], ee[c]);
                BL[(bN + c) * ARS + bKp] = packbf(bfres(oo[c]), bfres(ee[c]));
            }
        }
        __syncthreads();

        // ---- prefetch next tile (overlaps MMA) ----
        if (k0 + 16 < DD) {
            av0 = *reinterpret_cast<const float4*>(aPtr + k0 + 16);
            av1 = *reinterpret_cast<const float4*>(aPtr + k0 + 20);
            be  = *reinterpret_cast<const float4*>(bPtr + (size_t)(k0 + 16) * G3);
            bo  = *reinterpret_cast<const float4*>(bPtr + (size_t)(k0 + 16) * G3 + G3);
        }

        // ---- ldmatrix fragments + MMAs ----
        unsigned ahi[2][4], alo[2][4];
#pragma unroll
        for (int mt = 0; mt < 2; mt++) {
            ldsm_x4(ahi[mt][0], ahi[mt][1], ahi[mt][2], ahi[mt][3], aAdH[mt]);
            ldsm_x4(alo[mt][0], alo[mt][1], alo[mt][2], alo[mt][3], aAdL[mt]);
        }
#pragma unroll
        for (int np = 0; np < 4; np++) {
            unsigned bh[4], bl[4];
            ldsm_x4(bh[0], bh[1], bh[2], bh[3], bAdH[np]);
            ldsm_x4(bl[0], bl[1], bl[2], bl[3], bAdL[np]);
#pragma unroll
            for (int tile = 0; tile < 2; tile++) {
                const int nt = np * 2 + tile;
#pragma unroll
                for (int mt = 0; mt < 2; mt++) {
                    mma_bf16(acc[mt][nt], ahi[mt], bh[2 * tile], bh[2 * tile + 1]);
                    mma_bf16(acc[mt][nt], alo[mt], bh[2 * tile], bh[2 * tile + 1]);
                    mma_bf16(acc[mt][nt], ahi[mt], bl[2 * tile], bl[2 * tile + 1]);
                }
            }
        }
        __syncthreads();
    }

    // ---- epilogue ----
#pragma unroll
    for (int mt = 0; mt < 2; mt++) {
        const int m0 = mBase + warp_m * 32 + mt * 16 + gid;
        const int m1 = m0 + 8;
#pragma unroll
        for (int nt = 0; nt < 8; nt++) {
            const int col = jBase + warp_n * 64 + nt * 8 + tig * 2;
            const float2 bv = *reinterpret_cast<const float2*>(&bias[col]);
            float2 o0, o1;
            o0.x = acc[mt][nt][0] + bv.x;  o0.y = acc[mt][nt][1] + bv.y;
            o1.x = acc[mt][nt][2] + bv.x;  o1.y = acc[mt][nt][3] + bv.y;
            *reinterpret_cast<float2*>(&C[(size_t)m0 * G3 + col]) = o0;
            *reinterpret_cast<float2*>(&C[(size_t)m1 * G3 + col]) = o1;
        }
    }
}

// -----------------------------------------------------------------------------
// Persistent recurrence (tensor-core). Changes vs R7:
//  - h_prev fp32 kept in REGISTERS (each thread reuses its own gate outputs)
//  - xm gate inputs for step s+1 prefetched BEFORE the barrier
//  - release/acquire monotonic barrier (no threadfence, no reset)
// -----------------------------------------------------------------------------
#define BFRAG_UINTS  (32 * 3 * 32 * 4)           // 12288
#define REDF         (12 * 32 * 4)               // 1536 floats
#define PMMA_SMEM    ((BFRAG_UINTS + REDF) * 4)  // 55296 B
#define HB_PP        32768                       // uints per (dir,parity)

__global__ __launch_bounds__(256, 1) void gru_persist_mma_kernel(
    const float* __restrict__ Wh_f, const float* __restrict__ Wh_b,
    const float* __restrict__ xm, unsigned* __restrict__ hbf,
    float* __restrict__ out)
{
    extern __shared__ unsigned smu[];
    unsigned* bfr = smu;
    float* red = reinterpret_cast<float*>(smu + BFRAG_UINTS);

    const int dir = blockIdx.y;
    const int j0  = blockIdx.x * 8;
    const float* __restrict__ Wh = dir ? Wh_b : Wh_f;

    const int t  = threadIdx.x;
    const int w  = t >> 5;
    const int l  = t & 31;
    const int g  = l >> 2;
    const int tq = l & 3;
    const int mt = w & 3;
    const int khalf = w >> 2;

    // ---- fill W B-fragments once ----
    for (int idx = t; idx < 24 * 256; idx += 256) {
        const int c_loc = idx >> 8;
        const int k2    = idx & 255;
        const int gate  = c_loc >> 3;
        const int jj    = c_loc & 7;
        const int col   = gate * HH + j0 + jj;
        const float e = Wh[(size_t)(2 * k2) * G3 + col];
        const float o = Wh[(size_t)(2 * k2 + 1) * G3 + col];
        const int kt = k2 >> 3;
        const int pp = k2 & 7;
        const int rr = pp >> 2;
        const int ts = pp & 3;
        const int off4 = ((kt * 3 + gate) * 32 + jj * 4 + ts) * 4;
        bfr[off4 + rr]     = packbf(o, e);
        bfr[off4 + 2 + rr] = packbf(bfres(o), bfres(e));
    }
    __syncthreads();

    const int row0 = mt * 16 + g;
    const int row1 = row0 + 8;
    const int n0 = row0, n1 = row1;
    const int jA  = j0 + 2 * tq;
    const int k2g = (j0 >> 1) + tq;
    const int wkt = k2g >> 3;
    const int wpp = k2g & 7;
    const int wtq = wpp & 3;
    const int wsl = (wpp >> 2) * 2;
    const float* xmd = xm + (size_t)dir * (NB * TT) * G3;

    // persistent gate-input registers + register-resident h_prev
    float2 xz0, xr0, xg0, xz1, xr1, xg1;
    float2 hp0 = make_float2(0.f, 0.f), hp1 = make_float2(0.f, 0.f);
    if (khalf == 0) {
        const float* b0 = &xmd[((size_t)n0 * TT + 0) * G3 + jA];
        const float* b1 = &xmd[((size_t)n1 * TT + 0) * G3 + jA];
        xz0 = __ldg((const float2*)(b0));
        xr0 = __ldg((const float2*)(b0 + HH));
        xg0 = __ldg((const float2*)(b0 + 2 * HH));
        xz1 = __ldg((const float2*)(b1));
        xr1 = __ldg((const float2*)(b1 + HH));
        xg1 = __ldg((const float2*)(b1 + 2 * HH));
    }

    for (int s = 0; s < TT; s++) {
        const int p = s & 1;
        const unsigned* __restrict__ hb  = hbf + ((size_t)dir * 2 + p)       * HB_PP;
        unsigned*       __restrict__ hbn = hbf + ((size_t)dir * 2 + (p ^ 1)) * HB_PP;

        // ---- MMA mainloop ----
        float acc[3][4];
#pragma unroll
        for (int nt = 0; nt < 3; nt++)
#pragma unroll
            for (int r = 0; r < 4; r++) acc[nt][r] = 0.f;

        const int ktb = khalf * 16;
        uint4 v0[2], v1[2];
        {
            const int a = row0 * 512 + ktb * 16 + tq * 4;
            const int b = row1 * 512 + ktb * 16 + tq * 4;
            v0[0] = __ldg(reinterpret_cast<const uint4*>(&hb[a]));
            v1[0] = __ldg(reinterpret_cast<const uint4*>(&hb[b]));
        }
#pragma unroll
        for (int ki = 0; ki < 16; ki++) {
            const int kt  = ktb + ki;
            const int cur = ki & 1;
            if (ki < 15) {
                const int a = row0 * 512 + (kt + 1) * 16 + tq * 4;
                const int b = row1 * 512 + (kt + 1) * 16 + tq * 4;
                v0[cur ^ 1] = __ldg(reinterpret_cast<const uint4*>(&hb[a]));
                v1[cur ^ 1] = __ldg(reinterpret_cast<const uint4*>(&hb[b]));
            }
            unsigned aH[4], aL[4];
            aH[0] = v0[cur].x; aH[1] = v1[cur].x; aH[2] = v0[cur].z; aH[3] = v1[cur].z;
            aL[0] = v0[cur].y; aL[1] = v1[cur].y; aL[2] = v0[cur].w; aL[3] = v1[cur].w;
#pragma unroll
            for (int nt = 0; nt < 3; nt++) {
                const uint4 bb = *reinterpret_cast<const uint4*>(
                    &bfr[((kt * 3 + nt) * 32 + l) * 4]);
                mma_bf16(acc[nt], aH, bb.x, bb.y);
                mma_bf16(acc[nt], aL, bb.x, bb.y);
                mma_bf16(acc[nt], aH, bb.z, bb.w);
            }
        }

        // ---- split-K exchange ----
        if (khalf == 1) {
#pragma unroll
            for (int nt = 0; nt < 3; nt++) {
                float4 v = make_float4(acc[nt][0], acc[nt][1], acc[nt][2], acc[nt][3]);
                *reinterpret_cast<float4*>(&red[((mt * 3 + nt) * 32 + l) * 4]) = v;
            }
        }
        __syncthreads();

        if (khalf == 0) {
#pragma unroll
            for (int nt = 0; nt < 3; nt++) {
                const float4 v = *reinterpret_cast<const float4*>(
                    &red[((mt * 3 + nt) * 32 + l) * 4]);
                acc[nt][0] += v.x; acc[nt][1] += v.y;
                acc[nt][2] += v.z; acc[nt][3] += v.w;
            }
            const float z0a = 1.f / (1.f + __expf(-(xz0.x + acc[0][0])));
            const float z0b = 1.f / (1.f + __expf(-(xz0.y + acc[0][1])));
            const float z1a = 1.f / (1.f + __expf(-(xz1.x + acc[0][2])));
            const float z1b = 1.f / (1.f + __expf(-(xz1.y + acc[0][3])));
            const float r0a = 1.f / (1.f + __expf(-(xr0.x + acc[1][0])));
            const float r0b = 1.f / (1.f + __expf(-(xr0.y + acc[1][1])));
            const float r1a = 1.f / (1.f + __expf(-(xr1.x + acc[1][2])));
            const float r1b = 1.f / (1.f + __expf(-(xr1.y + acc[1][3])));
            const float g0a = tanhf(xg0.x + r0a * acc[2][0]);
            const float g0b = tanhf(xg0.y + r0b * acc[2][1]);
            const float g1a = tanhf(xg1.x + r1a * acc[2][2]);
            const float g1b = tanhf(xg1.y + r1b * acc[2][3]);
            const float h0a = (1.f - z0a) * g0a + z0a * hp0.x;
            const float h0b = (1.f - z0b) * g0b + z0b * hp0.y;
            const float h1a = (1.f - z1a) * g1a + z1a * hp1.x;
            const float h1b = (1.f - z1b) * g1b + z1b * hp1.y;
            hp0 = make_float2(h0a, h0b);
            hp1 = make_float2(h1a, h1b);

            const int t_out = dir ? (TT - 1 - s) : s;
            *reinterpret_cast<float2*>(
                &out[((size_t)n0 * TT + t_out) * (2 * HH) + dir * HH + jA]) =
                make_float2(h0a, h0b);
            *reinterpret_cast<float2*>(
                &out[((size_t)n1 * TT + t_out) * (2 * HH) + dir * HH + jA]) =
                make_float2(h1a, h1b);
            *reinterpret_cast<uint2*>(&hbn[n0 * 512 + wkt * 16 + wtq * 4 + wsl]) =
                make_uint2(packbf(h0b, h0a), packbf(bfres(h0b), bfres(h0a)));
            *reinterpret_cast<uint2*>(&hbn[n1 * 512 + wkt * 16 + wtq * 4 + wsl]) =
                make_uint2(packbf(h1b, h1a), packbf(bfres(h1b), bfres(h1a)));

            // ---- prefetch next step's gate inputs (before the barrier) ----
            if (s + 1 < TT) {
                const float* b0 = &xmd[((size_t)n0 * TT + (s + 1)) * G3 + jA];
                const float* b1 = &xmd[((size_t)n1 * TT + (s + 1)) * G3 + jA];
                xz0 = __ldg((const float2*)(b0));
                xr0 = __ldg((const float2*)(b0 + HH));
                xg0 = __ldg((const float2*)(b0 + 2 * HH));
                xz1 = __ldg((const float2*)(b1));
                xr1 = __ldg((const float2*)(b1 + HH));
                xg1 = __ldg((const float2*)(b1 + 2 * HH));
            }
        }

        // ---- per-direction release/acquire barrier (monotonic counter) ----
        __syncthreads();
        if (t == 0) {
            unsigned old;
            asm volatile("atom.add.release.gpu.u32 %0, [%1], 1;"
                         : "=r"(old) : "l"(&g_arrive[dir]) : "memory");
            const unsigned target = 64u * (unsigned)(s + 1);
            unsigned cur;
            do {
                asm volatile("ld.acquire.gpu.u32 %0, [%1];"
                             : "=r"(cur) : "l"(&g_arrive[dir]) : "memory");
            } while (cur < target);
        }
        __syncthreads();
    }
}

// -----------------------------------------------------------------------------
// Launch
// -----------------------------------------------------------------------------
extern "C" void kernel_launch(void* const* d_in, const int* in_sizes, int n_in,
                              void* d_out, int out_size)
{
    (void)in_sizes; (void)n_in; (void)out_size;
    const float* x   = (const float*)d_in[0];
    const float* Wxf = (const float*)d_in[1];
    const float* Whf = (const float*)d_in[2];
    const float* bf  = (const float*)d_in[3];
    const float* Wxb = (const float*)d_in[4];
    const float* Whb = (const float*)d_in[5];
    const float* bb  = (const float*)d_in[6];
    float* out = (float*)d_out;

    float* xm;
    unsigned* hbf;
    cudaGetSymbolAddress((void**)&xm, g_xm);
    cudaGetSymbolAddress((void**)&hbf, g_hbf);

    cudaFuncSetAttribute(gru_persist_mma_kernel,
                         cudaFuncAttributeMaxDynamicSharedMemorySize,
                         PMMA_SMEM);

    // 1) h bf16 buffers = 0, barrier counters = 0
    init_kernel<<<128, 256>>>(hbf);

    // 2) input projections: bf16 MMA + ldmatrix, pipelined
    sgemm_xm_bf16x3_kernel<<<dim3(12, 256, 2), 256>>>(x, Wxf, Wxb, bf, bb, xm);

    // 3) persistent recurrence
    gru_persist_mma_kernel<<<dim3(64, 2), 256, PMMA_SMEM>>>(
        Whf, Whb, xm, hbf, out);
}